// round 2
// baseline (speedup 1.0000x reference)
#include <cuda_runtime.h>
#include <math.h>

// Problem constants (fixed by the dataset)
#define NN   1000000
#define EE   16000000
#define H    16
#define DIN  16
#define HIDN 8
#define OUTN 2

// Scratch (static device globals — allowed; runtime alloc is not)
__device__ float g_xw[NN * H];    // x @ W_conv
__device__ float g_agg[NN * H];   // aggregated messages (incl. self-loop)
__device__ float g_deg[NN];       // degree (in-degree + 1)
__device__ float g_dis[NN];       // rsqrt(deg)

// ---------------------------------------------------------------------------
// K1: xw = x @ W_conv, deg = 1.0 (self loop seed)
// ---------------------------------------------------------------------------
__global__ void k1_xw_deg(const float* __restrict__ x,
                          const float* __restrict__ Wc, int n) {
    __shared__ float4 sW[DIN * 4];  // W_conv[k][j], 16 rows x 4 float4
    int tid = threadIdx.x;
    if (tid < DIN * 4) sW[tid] = ((const float4*)Wc)[tid];
    __syncthreads();

    int i = blockIdx.x * blockDim.x + tid;
    if (i >= n) return;

    const float4* xr = (const float4*)(x + (size_t)i * DIN);
    float4 xv0 = xr[0], xv1 = xr[1], xv2 = xr[2], xv3 = xr[3];
    float xk[16] = {xv0.x, xv0.y, xv0.z, xv0.w,
                    xv1.x, xv1.y, xv1.z, xv1.w,
                    xv2.x, xv2.y, xv2.z, xv2.w,
                    xv3.x, xv3.y, xv3.z, xv3.w};

    float4 a0 = make_float4(0.f, 0.f, 0.f, 0.f);
    float4 a1 = a0, a2 = a0, a3 = a0;
#pragma unroll
    for (int k = 0; k < 16; k++) {
        float v = xk[k];
        float4 w0 = sW[k * 4 + 0], w1 = sW[k * 4 + 1];
        float4 w2 = sW[k * 4 + 2], w3 = sW[k * 4 + 3];
        a0.x += v * w0.x; a0.y += v * w0.y; a0.z += v * w0.z; a0.w += v * w0.w;
        a1.x += v * w1.x; a1.y += v * w1.y; a1.z += v * w1.z; a1.w += v * w1.w;
        a2.x += v * w2.x; a2.y += v * w2.y; a2.z += v * w2.z; a2.w += v * w2.w;
        a3.x += v * w3.x; a3.y += v * w3.y; a3.z += v * w3.z; a3.w += v * w3.w;
    }
    float4* dst = (float4*)(g_xw + (size_t)i * H);
    dst[0] = a0; dst[1] = a1; dst[2] = a2; dst[3] = a3;
    g_deg[i] = 1.0f;
}

// ---------------------------------------------------------------------------
// K2: deg[col] += 1 over all edges (4 edges/thread, 16B int4 index loads)
// ---------------------------------------------------------------------------
__global__ void k2_deg(const int* __restrict__ colp, int e) {
    int i = (blockIdx.x * blockDim.x + threadIdx.x) * 4;
    if (i >= e) return;
    if (i + 3 < e) {
        int4 v = *(const int4*)(colp + i);
        atomicAdd(&g_deg[v.x], 1.0f);
        atomicAdd(&g_deg[v.y], 1.0f);
        atomicAdd(&g_deg[v.z], 1.0f);
        atomicAdd(&g_deg[v.w], 1.0f);
    } else {
        for (int k = i; k < e; k++) atomicAdd(&g_deg[colp[k]], 1.0f);
    }
}

// ---------------------------------------------------------------------------
// K3: dis = rsqrt(deg); agg = dis^2 * xw   (self-loop contribution seeds agg)
// ---------------------------------------------------------------------------
__global__ void k3_dis_self(int n) {
    int i = blockIdx.x * blockDim.x + threadIdx.x;
    if (i >= n) return;
    float dis = rsqrtf(g_deg[i]);
    g_dis[i] = dis;
    float s = dis * dis;
    const float4* xr = (const float4*)(g_xw + (size_t)i * H);
    float4* ar = (float4*)(g_agg + (size_t)i * H);
#pragma unroll
    for (int q = 0; q < 4; q++) {
        float4 v = xr[q];
        v.x *= s; v.y *= s; v.z *= s; v.w *= s;
        ar[q] = v;
    }
}

// ---------------------------------------------------------------------------
// K4: edge scatter — agg[col] += dis[row]*dis[col] * xw[row]
//     2 edges/thread (int2 index loads); red.global.add.v4.f32 (4 per edge)
// ---------------------------------------------------------------------------
__device__ __forceinline__ void red_v4(float* dst, float4 v) {
    asm volatile("red.global.add.v4.f32 [%0], {%1,%2,%3,%4};"
                 :: "l"(dst), "f"(v.x), "f"(v.y), "f"(v.z), "f"(v.w)
                 : "memory");
}

__device__ __forceinline__ void scatter_one(int r, int c) {
    float nrm = __ldg(&g_dis[r]) * __ldg(&g_dis[c]);
    const float4* xr = (const float4*)(g_xw + (size_t)r * H);
    float* dst = g_agg + (size_t)c * H;
#pragma unroll
    for (int q = 0; q < 4; q++) {
        float4 v = __ldg(xr + q);
        v.x *= nrm; v.y *= nrm; v.z *= nrm; v.w *= nrm;
        red_v4(dst + q * 4, v);
    }
}

__global__ void k4_scatter(const int* __restrict__ rowp,
                           const int* __restrict__ colp, int e) {
    int i = (blockIdx.x * blockDim.x + threadIdx.x) * 2;
    if (i >= e) return;
    if (i + 1 < e) {
        int2 rv = *(const int2*)(rowp + i);
        int2 cv = *(const int2*)(colp + i);
        scatter_one(rv.x, cv.x);
        scatter_one(rv.y, cv.y);
    } else {
        scatter_one(rowp[i], colp[i]);
    }
}

// ---------------------------------------------------------------------------
// K5: x_emb = relu(agg + b_conv); GRU(x_emb, Zt); fc1+relu; fc2
//     16 threads per node (thread j owns output feature j, weight columns in
//     registers, hoisted over a persistent tile loop). Warp-local shared
//     exchange only -> __syncwarp.
// ---------------------------------------------------------------------------
__global__ void __launch_bounds__(256, 2)
k5_gru(const float* __restrict__ Zt, const int* __restrict__ firstp,
       const float* __restrict__ bconv,
       const float* __restrict__ Wir, const float* __restrict__ bir,
       const float* __restrict__ Whr, const float* __restrict__ bhr,
       const float* __restrict__ Wiz, const float* __restrict__ biz,
       const float* __restrict__ Whz, const float* __restrict__ bhz,
       const float* __restrict__ Win, const float* __restrict__ bin_,
       const float* __restrict__ Whn, const float* __restrict__ bhn,
       const float* __restrict__ Wf1, const float* __restrict__ bf1,
       const float* __restrict__ Wf2, const float* __restrict__ bf2,
       float* __restrict__ out_final, float* __restrict__ out_zbar, int n) {
    __shared__ float sA[16][16];
    __shared__ float sB[16][16];
    __shared__ float sZ[16][16];
    __shared__ float sHd[16][HIDN];

    int tid = threadIdx.x;
    int j = tid & 15;
    int nl = tid >> 4;

    // Per-thread weight columns (column j of each gate matrix)
    float wir[16], whr[16], wiz[16], whz[16], win[16], whn[16];
#pragma unroll
    for (int k = 0; k < 16; k++) {
        wir[k] = Wir[k * 16 + j];
        whr[k] = Whr[k * 16 + j];
        wiz[k] = Wiz[k * 16 + j];
        whz[k] = Whz[k * 16 + j];
        win[k] = Win[k * 16 + j];
        whn[k] = Whn[k * 16 + j];
    }
    float cb  = bconv[j];
    float brz = bir[j] + bhr[j];
    float bzz = biz[j] + bhz[j];
    float bni = bin_[j];
    float bnh = bhn[j];
    float bf1r = (j < HIDN) ? bf1[j] : 0.f;
    float bf2r = (j < OUTN) ? bf2[j] : 0.f;
    int first = firstp[0];

    int ntiles = n >> 4;  // 16 nodes per tile (block handles 16 nodes/iter)
    for (int t = blockIdx.x; t < ntiles; t += gridDim.x) {
        int base = t * 256;

        float a = g_agg[base + tid] + cb;
        a = a > 0.f ? a : 0.f;
        float b = Zt[base + tid];
        sA[nl][j] = a;
        sB[nl][j] = b;
        __syncwarp();

        float accr = brz, accz = bzz, accni = bni, accnh = bnh;
#pragma unroll
        for (int k = 0; k < 16; k++) {
            float ak = sA[nl][k];
            float bk = sB[nl][k];
            accr  += ak * wir[k] + bk * whr[k];
            accz  += ak * wiz[k] + bk * whz[k];
            accni += ak * win[k];
            accnh += bk * whn[k];
        }

        float zb;
        if (first) {
            zb = a;
        } else {
            float r  = 1.f / (1.f + expf(-accr));
            float z  = 1.f / (1.f + expf(-accz));
            float nn = tanhf(accni + r * accnh);
            zb = (1.f - z) * nn + z * b;
        }
        out_zbar[base + tid] = zb;
        sZ[nl][j] = zb;
        __syncwarp();

        if (j < HIDN) {
            float h = bf1r;
#pragma unroll
            for (int k = 0; k < 16; k++)
                h += sZ[nl][k] * __ldg(Wf1 + k * HIDN + j);
            h = h > 0.f ? h : 0.f;
            sHd[nl][j] = h;
        }
        __syncwarp();

        if (j < OUTN) {
            float o = bf2r;
#pragma unroll
            for (int k = 0; k < HIDN; k++)
                o += sHd[nl][k] * __ldg(Wf2 + k * OUTN + j);
            int node = t * 16 + nl;
            out_final[node * OUTN + j] = o;
        }
        __syncwarp();  // protect shared reuse across tile iterations
    }
}

// ---------------------------------------------------------------------------
// launch
// ---------------------------------------------------------------------------
extern "C" void kernel_launch(void* const* d_in, const int* in_sizes, int n_in,
                              void* d_out, int out_size) {
    const float* x      = (const float*)d_in[0];
    const int*   ei     = (const int*)d_in[1];     // int32 (JAX default, no x64)
    const float* Zt     = (const float*)d_in[2];
    const int*   firstp = (const int*)d_in[3];
    const float* W_conv = (const float*)d_in[4];
    const float* b_conv = (const float*)d_in[5];
    const float* W_ir   = (const float*)d_in[6];
    const float* b_ir   = (const float*)d_in[7];
    const float* W_hr   = (const float*)d_in[8];
    const float* b_hr   = (const float*)d_in[9];
    const float* W_iz   = (const float*)d_in[10];
    const float* b_iz   = (const float*)d_in[11];
    const float* W_hz   = (const float*)d_in[12];
    const float* b_hz   = (const float*)d_in[13];
    const float* W_in   = (const float*)d_in[14];
    const float* b_in   = (const float*)d_in[15];
    const float* W_hn   = (const float*)d_in[16];
    const float* b_hn   = (const float*)d_in[17];
    const float* W_fc1  = (const float*)d_in[18];
    const float* b_fc1  = (const float*)d_in[19];
    const float* W_fc2  = (const float*)d_in[20];
    const float* b_fc2  = (const float*)d_in[21];

    const int n = in_sizes[0] / DIN;       // 1,000,000
    const int e = in_sizes[1] / 2;         // 16,000,000
    const int* rowp = ei;                  // edge_index[0] (sources)
    const int* colp = ei + e;              // edge_index[1] (targets)

    float* out_final = (float*)d_out;                     // [N, 2]
    float* out_zbar  = (float*)d_out + (size_t)n * OUTN;  // [N, 16]

    const int TPB = 256;
    // K1: xw + deg seed
    k1_xw_deg<<<(n + TPB - 1) / TPB, TPB>>>(x, W_conv, n);
    // K2: degree accumulation
    k2_deg<<<(e / 4 + TPB - 1) / TPB, TPB>>>(colp, e);
    // K3: dis + self-loop seed of agg
    k3_dis_self<<<(n + TPB - 1) / TPB, TPB>>>(n);
    // K4: edge scatter (dominant)
    k4_scatter<<<(e / 2 + TPB - 1) / TPB, TPB>>>(rowp, colp, e);
    // K5: GRU + FC (persistent grid)
    k5_gru<<<148 * 8, TPB>>>(Zt, firstp, b_conv,
                             W_ir, b_ir, W_hr, b_hr,
                             W_iz, b_iz, W_hz, b_hz,
                             W_in, b_in, W_hn, b_hn,
                             W_fc1, b_fc1, W_fc2, b_fc2,
                             out_final, out_zbar, n);
}

// round 3
// speedup vs baseline: 1.0222x; 1.0222x over previous
#include <cuda_runtime.h>
#include <math.h>

#define NN   1000000
#define H    16
#define DIN  16
#define HIDN 8
#define OUTN 2

// Scratch (static device globals). g_cnt starts 0 (module load) and is reset
// to 0 by k3 after consumption -> deterministic across graph replays.
__device__ float g_xw[NN * H];    // x @ W_conv, later overwritten by dis[r]*xw[r]
__device__ float g_agg[NN * H];   // scatter target (seeded with self-loop term)
__device__ float g_cnt[NN];       // in-degree count (excl. self loop)
__device__ float g_dis[NN];       // rsqrt(1 + cnt)

// ---------------------------------------------------------------------------
// K12 fused: blocks [0,B1) compute xw = x@W_conv; blocks [B1,..) count degree
// ---------------------------------------------------------------------------
__global__ void k12_xw_deg(const float* __restrict__ x,
                           const float* __restrict__ Wc,
                           const int* __restrict__ colp,
                           int n, int e, int B1) {
    int tid = threadIdx.x;
    if ((int)blockIdx.x < B1) {
        // ---- K1 part: xw = x @ W_conv ----
        __shared__ float4 sW[DIN * 4];
        if (tid < DIN * 4) sW[tid] = ((const float4*)Wc)[tid];
        __syncthreads();

        int i = blockIdx.x * blockDim.x + tid;
        if (i >= n) return;

        const float4* xr = (const float4*)(x + (size_t)i * DIN);
        float4 xv0 = xr[0], xv1 = xr[1], xv2 = xr[2], xv3 = xr[3];
        float xk[16] = {xv0.x, xv0.y, xv0.z, xv0.w,
                        xv1.x, xv1.y, xv1.z, xv1.w,
                        xv2.x, xv2.y, xv2.z, xv2.w,
                        xv3.x, xv3.y, xv3.z, xv3.w};

        float4 a0 = make_float4(0.f, 0.f, 0.f, 0.f);
        float4 a1 = a0, a2 = a0, a3 = a0;
#pragma unroll
        for (int k = 0; k < 16; k++) {
            float v = xk[k];
            float4 w0 = sW[k * 4 + 0], w1 = sW[k * 4 + 1];
            float4 w2 = sW[k * 4 + 2], w3 = sW[k * 4 + 3];
            a0.x += v * w0.x; a0.y += v * w0.y; a0.z += v * w0.z; a0.w += v * w0.w;
            a1.x += v * w1.x; a1.y += v * w1.y; a1.z += v * w1.z; a1.w += v * w1.w;
            a2.x += v * w2.x; a2.y += v * w2.y; a2.z += v * w2.z; a2.w += v * w2.w;
            a3.x += v * w3.x; a3.y += v * w3.y; a3.z += v * w3.z; a3.w += v * w3.w;
        }
        float4* dst = (float4*)(g_xw + (size_t)i * H);
        dst[0] = a0; dst[1] = a1; dst[2] = a2; dst[3] = a3;
    } else {
        // ---- K2 part: cnt[col] += 1 over all edges (4 edges/thread) ----
        int i = ((blockIdx.x - B1) * blockDim.x + tid) * 4;
        if (i >= e) return;
        if (i + 3 < e) {
            int4 v = *(const int4*)(colp + i);
            atomicAdd(&g_cnt[v.x], 1.0f);
            atomicAdd(&g_cnt[v.y], 1.0f);
            atomicAdd(&g_cnt[v.z], 1.0f);
            atomicAdd(&g_cnt[v.w], 1.0f);
        } else {
            for (int k = i; k < e; k++) atomicAdd(&g_cnt[colp[k]], 1.0f);
        }
    }
}

// ---------------------------------------------------------------------------
// K3: dis = rsqrt(1+cnt); cnt = 0 (replay determinism);
//     xw <- dis*xw (pre-scaled by source norm); agg <- dis*xw (self-loop seed,
//     since self term = dis^2*xw and K5 multiplies agg by dis once more)
// ---------------------------------------------------------------------------
__global__ void k3_dis_scale(int n) {
    int i = blockIdx.x * blockDim.x + threadIdx.x;
    if (i >= n) return;
    float dis = rsqrtf(1.0f + g_cnt[i]);
    g_cnt[i] = 0.0f;
    g_dis[i] = dis;
    float4* xr = (float4*)(g_xw + (size_t)i * H);
    float4* ar = (float4*)(g_agg + (size_t)i * H);
#pragma unroll
    for (int q = 0; q < 4; q++) {
        float4 v = xr[q];
        v.x *= dis; v.y *= dis; v.z *= dis; v.w *= dis;
        xr[q] = v;
        ar[q] = v;
    }
}

// ---------------------------------------------------------------------------
// K4: agg[col] += xw_s[row]  — pure gather + vector RED, no arithmetic.
//     4 edges/thread, int4 index loads.
// ---------------------------------------------------------------------------
__device__ __forceinline__ void red_v4(float* dst, float4 v) {
    asm volatile("red.global.add.v4.f32 [%0], {%1,%2,%3,%4};"
                 :: "l"(dst), "f"(v.x), "f"(v.y), "f"(v.z), "f"(v.w)
                 : "memory");
}

__device__ __forceinline__ void scatter_one(int r, int c) {
    const float4* xr = (const float4*)(g_xw + (size_t)r * H);
    float* dst = g_agg + (size_t)c * H;
    float4 v0 = __ldg(xr + 0);
    float4 v1 = __ldg(xr + 1);
    float4 v2 = __ldg(xr + 2);
    float4 v3 = __ldg(xr + 3);
    red_v4(dst + 0,  v0);
    red_v4(dst + 4,  v1);
    red_v4(dst + 8,  v2);
    red_v4(dst + 12, v3);
}

__global__ void k4_scatter(const int* __restrict__ rowp,
                           const int* __restrict__ colp, int e) {
    int i = (blockIdx.x * blockDim.x + threadIdx.x) * 4;
    if (i >= e) return;
    if (i + 3 < e) {
        int4 rv = *(const int4*)(rowp + i);
        int4 cv = *(const int4*)(colp + i);
        scatter_one(rv.x, cv.x);
        scatter_one(rv.y, cv.y);
        scatter_one(rv.z, cv.z);
        scatter_one(rv.w, cv.w);
    } else {
        for (int k = i; k < e; k++) scatter_one(rowp[k], colp[k]);
    }
}

// ---------------------------------------------------------------------------
// K5: x_emb = relu(dis[i]*agg[i] + b_conv); GRU(x_emb, Zt); fc1+relu; fc2
// ---------------------------------------------------------------------------
__global__ void __launch_bounds__(256, 2)
k5_gru(const float* __restrict__ Zt, const int* __restrict__ firstp,
       const float* __restrict__ bconv,
       const float* __restrict__ Wir, const float* __restrict__ bir,
       const float* __restrict__ Whr, const float* __restrict__ bhr,
       const float* __restrict__ Wiz, const float* __restrict__ biz,
       const float* __restrict__ Whz, const float* __restrict__ bhz,
       const float* __restrict__ Win, const float* __restrict__ bin_,
       const float* __restrict__ Whn, const float* __restrict__ bhn,
       const float* __restrict__ Wf1, const float* __restrict__ bf1,
       const float* __restrict__ Wf2, const float* __restrict__ bf2,
       float* __restrict__ out_final, float* __restrict__ out_zbar, int n) {
    __shared__ float sA[16][16];
    __shared__ float sB[16][16];
    __shared__ float sZ[16][16];
    __shared__ float sHd[16][HIDN];

    int tid = threadIdx.x;
    int j = tid & 15;
    int nl = tid >> 4;

    float wir[16], whr[16], wiz[16], whz[16], win[16], whn[16];
#pragma unroll
    for (int k = 0; k < 16; k++) {
        wir[k] = Wir[k * 16 + j];
        whr[k] = Whr[k * 16 + j];
        wiz[k] = Wiz[k * 16 + j];
        whz[k] = Whz[k * 16 + j];
        win[k] = Win[k * 16 + j];
        whn[k] = Whn[k * 16 + j];
    }
    float cb  = bconv[j];
    float brz = bir[j] + bhr[j];
    float bzz = biz[j] + bhz[j];
    float bni = bin_[j];
    float bnh = bhn[j];
    float bf1r = (j < HIDN) ? bf1[j] : 0.f;
    float bf2r = (j < OUTN) ? bf2[j] : 0.f;
    int first = firstp[0];

    int ntiles = n >> 4;
    for (int t = blockIdx.x; t < ntiles; t += gridDim.x) {
        int base = t * 256;
        int node = t * 16 + nl;

        float dnode = __ldg(&g_dis[node]);
        float a = dnode * g_agg[base + tid] + cb;
        a = a > 0.f ? a : 0.f;
        float b = Zt[base + tid];
        sA[nl][j] = a;
        sB[nl][j] = b;
        __syncwarp();

        float accr = brz, accz = bzz, accni = bni, accnh = bnh;
#pragma unroll
        for (int k = 0; k < 16; k++) {
            float ak = sA[nl][k];
            float bk = sB[nl][k];
            accr  += ak * wir[k] + bk * whr[k];
            accz  += ak * wiz[k] + bk * whz[k];
            accni += ak * win[k];
            accnh += bk * whn[k];
        }

        float zb;
        if (first) {
            zb = a;
        } else {
            float r  = 1.f / (1.f + expf(-accr));
            float z  = 1.f / (1.f + expf(-accz));
            float nn = tanhf(accni + r * accnh);
            zb = (1.f - z) * nn + z * b;
        }
        out_zbar[base + tid] = zb;
        sZ[nl][j] = zb;
        __syncwarp();

        if (j < HIDN) {
            float h = bf1r;
#pragma unroll
            for (int k = 0; k < 16; k++)
                h += sZ[nl][k] * __ldg(Wf1 + k * HIDN + j);
            h = h > 0.f ? h : 0.f;
            sHd[nl][j] = h;
        }
        __syncwarp();

        if (j < OUTN) {
            float o = bf2r;
#pragma unroll
            for (int k = 0; k < HIDN; k++)
                o += sHd[nl][k] * __ldg(Wf2 + k * OUTN + j);
            out_final[node * OUTN + j] = o;
        }
        __syncwarp();
    }
}

// ---------------------------------------------------------------------------
// launch
// ---------------------------------------------------------------------------
extern "C" void kernel_launch(void* const* d_in, const int* in_sizes, int n_in,
                              void* d_out, int out_size) {
    const float* x      = (const float*)d_in[0];
    const int*   ei     = (const int*)d_in[1];
    const float* Zt     = (const float*)d_in[2];
    const int*   firstp = (const int*)d_in[3];
    const float* W_conv = (const float*)d_in[4];
    const float* b_conv = (const float*)d_in[5];
    const float* W_ir   = (const float*)d_in[6];
    const float* b_ir   = (const float*)d_in[7];
    const float* W_hr   = (const float*)d_in[8];
    const float* b_hr   = (const float*)d_in[9];
    const float* W_iz   = (const float*)d_in[10];
    const float* b_iz   = (const float*)d_in[11];
    const float* W_hz   = (const float*)d_in[12];
    const float* b_hz   = (const float*)d_in[13];
    const float* W_in   = (const float*)d_in[14];
    const float* b_in   = (const float*)d_in[15];
    const float* W_hn   = (const float*)d_in[16];
    const float* b_hn   = (const float*)d_in[17];
    const float* W_fc1  = (const float*)d_in[18];
    const float* b_fc1  = (const float*)d_in[19];
    const float* W_fc2  = (const float*)d_in[20];
    const float* b_fc2  = (const float*)d_in[21];

    const int n = in_sizes[0] / DIN;   // 1,000,000
    const int e = in_sizes[1] / 2;     // 16,000,000
    const int* rowp = ei;
    const int* colp = ei + e;

    float* out_final = (float*)d_out;
    float* out_zbar  = (float*)d_out + (size_t)n * OUTN;

    const int TPB = 256;
    const int B1 = (n + TPB - 1) / TPB;                 // xw blocks
    const int B2 = (e / 4 + TPB - 1) / TPB;             // degree blocks

    k12_xw_deg<<<B1 + B2, TPB>>>(x, W_conv, colp, n, e, B1);
    k3_dis_scale<<<(n + TPB - 1) / TPB, TPB>>>(n);
    k4_scatter<<<(e / 4 + TPB - 1) / TPB, TPB>>>(rowp, colp, e);
    k5_gru<<<148 * 8, TPB>>>(Zt, firstp, b_conv,
                             W_ir, b_ir, W_hr, b_hr,
                             W_iz, b_iz, W_hz, b_hz,
                             W_in, b_in, W_hn, b_hn,
                             W_fc1, b_fc1, W_fc2, b_fc2,
                             out_final, out_zbar, n);
}

// round 4
// speedup vs baseline: 1.0669x; 1.0438x over previous
#include <cuda_runtime.h>
#include <math.h>

#define NN   1000000
#define H    16
#define DIN  16
#define HIDN 8
#define OUTN 2

typedef unsigned long long ull;

// Scratch (static device globals). g_cnt starts 0 (module load) and is reset
// to 0 by k3 after consumption -> deterministic across graph replays.
__device__ float g_xw[NN * H];    // x @ W_conv, later overwritten by dis[r]*xw[r]
__device__ float g_agg[NN * H];   // scatter target (seeded with self-loop term)
__device__ float g_cnt[NN];       // in-degree count (excl. self loop)
__device__ float g_dis[NN];       // rsqrt(1 + cnt)

// ---------------------------------------------------------------------------
// f32x2 packed helpers (ptxas never emits FFMA2 from C++; PTX only)
// ---------------------------------------------------------------------------
__device__ __forceinline__ ull pack2(float lo, float hi) {
    ull r; asm("mov.b64 %0, {%1,%2};" : "=l"(r) : "f"(lo), "f"(hi)); return r;
}
__device__ __forceinline__ void unpack2(float& lo, float& hi, ull v) {
    asm("mov.b64 {%0,%1}, %2;" : "=f"(lo), "=f"(hi) : "l"(v));
}
__device__ __forceinline__ void fma2(ull& acc, ull a, ull b) {
    asm("fma.rn.f32x2 %0, %1, %2, %0;" : "+l"(acc) : "l"(a), "l"(b));
}

// ---------------------------------------------------------------------------
// K12 fused: blocks [0,B1) compute xw = x@W_conv; blocks [B1,..) count degree
// ---------------------------------------------------------------------------
__global__ void k12_xw_deg(const float* __restrict__ x,
                           const float* __restrict__ Wc,
                           const int* __restrict__ colp,
                           int n, int e, int B1) {
    int tid = threadIdx.x;
    if ((int)blockIdx.x < B1) {
        __shared__ float4 sW[DIN * 4];
        if (tid < DIN * 4) sW[tid] = ((const float4*)Wc)[tid];
        __syncthreads();

        int i = blockIdx.x * blockDim.x + tid;
        if (i >= n) return;

        const float4* xr = (const float4*)(x + (size_t)i * DIN);
        float4 xv0 = xr[0], xv1 = xr[1], xv2 = xr[2], xv3 = xr[3];
        float xk[16] = {xv0.x, xv0.y, xv0.z, xv0.w,
                        xv1.x, xv1.y, xv1.z, xv1.w,
                        xv2.x, xv2.y, xv2.z, xv2.w,
                        xv3.x, xv3.y, xv3.z, xv3.w};

        float4 a0 = make_float4(0.f, 0.f, 0.f, 0.f);
        float4 a1 = a0, a2 = a0, a3 = a0;
#pragma unroll
        for (int k = 0; k < 16; k++) {
            float v = xk[k];
            float4 w0 = sW[k * 4 + 0], w1 = sW[k * 4 + 1];
            float4 w2 = sW[k * 4 + 2], w3 = sW[k * 4 + 3];
            a0.x += v * w0.x; a0.y += v * w0.y; a0.z += v * w0.z; a0.w += v * w0.w;
            a1.x += v * w1.x; a1.y += v * w1.y; a1.z += v * w1.z; a1.w += v * w1.w;
            a2.x += v * w2.x; a2.y += v * w2.y; a2.z += v * w2.z; a2.w += v * w2.w;
            a3.x += v * w3.x; a3.y += v * w3.y; a3.z += v * w3.z; a3.w += v * w3.w;
        }
        float4* dst = (float4*)(g_xw + (size_t)i * H);
        dst[0] = a0; dst[1] = a1; dst[2] = a2; dst[3] = a3;
    } else {
        int i = ((blockIdx.x - B1) * blockDim.x + tid) * 4;
        if (i >= e) return;
        if (i + 3 < e) {
            int4 v = *(const int4*)(colp + i);
            atomicAdd(&g_cnt[v.x], 1.0f);
            atomicAdd(&g_cnt[v.y], 1.0f);
            atomicAdd(&g_cnt[v.z], 1.0f);
            atomicAdd(&g_cnt[v.w], 1.0f);
        } else {
            for (int k = i; k < e; k++) atomicAdd(&g_cnt[colp[k]], 1.0f);
        }
    }
}

// ---------------------------------------------------------------------------
// K3: dis = rsqrt(1+cnt); cnt = 0; xw <- dis*xw; agg <- dis*xw (self-loop)
// ---------------------------------------------------------------------------
__global__ void k3_dis_scale(int n) {
    int i = blockIdx.x * blockDim.x + threadIdx.x;
    if (i >= n) return;
    float dis = rsqrtf(1.0f + g_cnt[i]);
    g_cnt[i] = 0.0f;
    g_dis[i] = dis;
    float4* xr = (float4*)(g_xw + (size_t)i * H);
    float4* ar = (float4*)(g_agg + (size_t)i * H);
#pragma unroll
    for (int q = 0; q < 4; q++) {
        float4 v = xr[q];
        v.x *= dis; v.y *= dis; v.z *= dis; v.w *= dis;
        xr[q] = v;
        ar[q] = v;
    }
}

// ---------------------------------------------------------------------------
// K4: agg[col] += xw_s[row]  — pure gather + vector RED.
// ---------------------------------------------------------------------------
__device__ __forceinline__ void red_v4(float* dst, float4 v) {
    asm volatile("red.global.add.v4.f32 [%0], {%1,%2,%3,%4};"
                 :: "l"(dst), "f"(v.x), "f"(v.y), "f"(v.z), "f"(v.w)
                 : "memory");
}

__device__ __forceinline__ void scatter_one(int r, int c) {
    const float4* xr = (const float4*)(g_xw + (size_t)r * H);
    float* dst = g_agg + (size_t)c * H;
    float4 v0 = __ldg(xr + 0);
    float4 v1 = __ldg(xr + 1);
    float4 v2 = __ldg(xr + 2);
    float4 v3 = __ldg(xr + 3);
    red_v4(dst + 0,  v0);
    red_v4(dst + 4,  v1);
    red_v4(dst + 8,  v2);
    red_v4(dst + 12, v3);
}

__global__ void k4_scatter(const int* __restrict__ rowp,
                           const int* __restrict__ colp, int e) {
    int i = (blockIdx.x * blockDim.x + threadIdx.x) * 4;
    if (i >= e) return;
    if (i + 3 < e) {
        int4 rv = *(const int4*)(rowp + i);
        int4 cv = *(const int4*)(colp + i);
        scatter_one(rv.x, cv.x);
        scatter_one(rv.y, cv.y);
        scatter_one(rv.z, cv.z);
        scatter_one(rv.w, cv.w);
    } else {
        for (int k = i; k < e; k++) scatter_one(rowp[k], colp[k]);
    }
}

// ---------------------------------------------------------------------------
// K5: x_emb = relu(dis*agg + b_conv); GRU; fc1+relu; fc2
//     f32x2 packed gate accumulation: accX2 += (a_k,b_k)*(W_i[k][j],W_h[k][j])
//     MUFU transcendentals (__expf / __fdividef).
// ---------------------------------------------------------------------------
__global__ void __launch_bounds__(256, 2)
k5_gru(const float* __restrict__ Zt, const int* __restrict__ firstp,
       const float* __restrict__ bconv,
       const float* __restrict__ Wir, const float* __restrict__ bir,
       const float* __restrict__ Whr, const float* __restrict__ bhr,
       const float* __restrict__ Wiz, const float* __restrict__ biz,
       const float* __restrict__ Whz, const float* __restrict__ bhz,
       const float* __restrict__ Win, const float* __restrict__ bin_,
       const float* __restrict__ Whn, const float* __restrict__ bhn,
       const float* __restrict__ Wf1, const float* __restrict__ bf1,
       const float* __restrict__ Wf2, const float* __restrict__ bf2,
       float* __restrict__ out_final, float* __restrict__ out_zbar, int n) {
    __shared__ float2 sAB[16][16];     // (a_k, b_k) interleaved per node row
    __shared__ float  sZ[16][16];
    __shared__ float  sHd[16][HIDN];
    __shared__ float  sWf1[16 * HIDN];
    __shared__ float  sWf2[HIDN * OUTN];

    int tid = threadIdx.x;
    int j = tid & 15;
    int nl = tid >> 4;

    if (tid < 16 * HIDN) sWf1[tid] = Wf1[tid];
    if (tid < HIDN * OUTN) sWf2[tid] = Wf2[tid];

    // Packed weight pairs: column j of (input-gate, hidden-gate) matrices
    ull pr[16], pz[16], pn[16];
#pragma unroll
    for (int k = 0; k < 16; k++) {
        pr[k] = pack2(Wir[k * 16 + j], Whr[k * 16 + j]);
        pz[k] = pack2(Wiz[k * 16 + j], Whz[k * 16 + j]);
        pn[k] = pack2(Win[k * 16 + j], Whn[k * 16 + j]);
    }
    float cb   = bconv[j];
    ull   br2  = pack2(bir[j] + bhr[j], 0.f);   // seed accr2 with bias
    ull   bz2  = pack2(biz[j] + bhz[j], 0.f);
    ull   bn2  = pack2(bin_[j], bhn[j]);        // lo: accni bias, hi: accnh bias
    float bf1r = (j < HIDN) ? bf1[j] : 0.f;
    float bf2r = (j < OUTN) ? bf2[j] : 0.f;
    int first = firstp[0];
    __syncthreads();

    int ntiles = n >> 4;
    for (int t = blockIdx.x; t < ntiles; t += gridDim.x) {
        int base = t * 256;
        int node = t * 16 + nl;

        float dnode = __ldg(&g_dis[node]);
        float a = fmaf(dnode, g_agg[base + tid], cb);
        a = a > 0.f ? a : 0.f;
        float b = Zt[base + tid];
        sAB[nl][j] = make_float2(a, b);
        __syncwarp();

        ull r2 = br2, z2 = bz2, n2 = bn2;
        const ull* ab = (const ull*)sAB[nl];
#pragma unroll
        for (int k = 0; k < 16; k++) {
            ull t2 = ab[k];
            fma2(r2, t2, pr[k]);
            fma2(z2, t2, pz[k]);
            fma2(n2, t2, pn[k]);
        }
        float rl, rh, zl, zh, nlv, nhv;
        unpack2(rl, rh, r2);
        unpack2(zl, zh, z2);
        unpack2(nlv, nhv, n2);
        float accr = rl + rh;
        float accz = zl + zh;

        float zb;
        if (first) {
            zb = a;
        } else {
            float r  = __fdividef(1.f, 1.f + __expf(-accr));
            float z  = __fdividef(1.f, 1.f + __expf(-accz));
            float tn = fmaf(r, nhv, nlv);
            float nn = __fdividef(2.f, 1.f + __expf(-2.f * tn)) - 1.f;
            zb = (1.f - z) * nn + z * b;
        }
        out_zbar[base + tid] = zb;
        sZ[nl][j] = zb;
        __syncwarp();

        if (j < HIDN) {
            float h = bf1r;
#pragma unroll
            for (int k = 0; k < 16; k++)
                h += sZ[nl][k] * sWf1[k * HIDN + j];
            h = h > 0.f ? h : 0.f;
            sHd[nl][j] = h;
        }
        __syncwarp();

        if (j < OUTN) {
            float o = bf2r;
#pragma unroll
            for (int k = 0; k < HIDN; k++)
                o += sHd[nl][k] * sWf2[k * OUTN + j];
            out_final[node * OUTN + j] = o;
        }
        __syncwarp();
    }
}

// ---------------------------------------------------------------------------
// launch
// ---------------------------------------------------------------------------
extern "C" void kernel_launch(void* const* d_in, const int* in_sizes, int n_in,
                              void* d_out, int out_size) {
    const float* x      = (const float*)d_in[0];
    const int*   ei     = (const int*)d_in[1];
    const float* Zt     = (const float*)d_in[2];
    const int*   firstp = (const int*)d_in[3];
    const float* W_conv = (const float*)d_in[4];
    const float* b_conv = (const float*)d_in[5];
    const float* W_ir   = (const float*)d_in[6];
    const float* b_ir   = (const float*)d_in[7];
    const float* W_hr   = (const float*)d_in[8];
    const float* b_hr   = (const float*)d_in[9];
    const float* W_iz   = (const float*)d_in[10];
    const float* b_iz   = (const float*)d_in[11];
    const float* W_hz   = (const float*)d_in[12];
    const float* b_hz   = (const float*)d_in[13];
    const float* W_in   = (const float*)d_in[14];
    const float* b_in   = (const float*)d_in[15];
    const float* W_hn   = (const float*)d_in[16];
    const float* b_hn   = (const float*)d_in[17];
    const float* W_fc1  = (const float*)d_in[18];
    const float* b_fc1  = (const float*)d_in[19];
    const float* W_fc2  = (const float*)d_in[20];
    const float* b_fc2  = (const float*)d_in[21];

    const int n = in_sizes[0] / DIN;   // 1,000,000
    const int e = in_sizes[1] / 2;     // 16,000,000
    const int* rowp = ei;
    const int* colp = ei + e;

    float* out_final = (float*)d_out;
    float* out_zbar  = (float*)d_out + (size_t)n * OUTN;

    const int TPB = 256;
    const int B1 = (n + TPB - 1) / TPB;
    const int B2 = (e / 4 + TPB - 1) / TPB;

    k12_xw_deg<<<B1 + B2, TPB>>>(x, W_conv, colp, n, e, B1);
    k3_dis_scale<<<(n + TPB - 1) / TPB, TPB>>>(n);
    k4_scatter<<<(e / 4 + TPB - 1) / TPB, TPB>>>(rowp, colp, e);
    k5_gru<<<148 * 8, TPB>>>(Zt, firstp, b_conv,
                             W_ir, b_ir, W_hr, b_hr,
                             W_iz, b_iz, W_hz, b_hz,
                             W_in, b_in, W_hn, b_hn,
                             W_fc1, b_fc1, W_fc2, b_fc2,
                             out_final, out_zbar, n);
}

// round 5
// speedup vs baseline: 1.1989x; 1.1237x over previous
#include <cuda_runtime.h>
#include <cuda_fp16.h>
#include <math.h>

#define NN   1000000
#define H    16
#define DIN  16
#define HIDN 8
#define OUTN 2

typedef unsigned long long ull;

// Scratch (static device globals). g_cnt starts 0 (module load) and is reset
// to 0 by k3 after consumption -> deterministic across graph replays.
__device__ float  g_xw[NN * H];     // x @ W_conv (fp32, K12 -> K3)
__device__ __half g_xwh[NN * H];    // dis[r]*xw[r] in fp16 (gather table, 32MB)
__device__ float  g_agg[NN * H];    // scatter target (fp32, self-loop seeded)
__device__ float  g_cnt[NN];        // in-degree count (excl. self loop)
__device__ float  g_dis[NN];        // rsqrt(1 + cnt)

// ---------------------------------------------------------------------------
// f32x2 packed helpers (ptxas never emits FFMA2 from C++; PTX only)
// ---------------------------------------------------------------------------
__device__ __forceinline__ ull pack2(float lo, float hi) {
    ull r; asm("mov.b64 %0, {%1,%2};" : "=l"(r) : "f"(lo), "f"(hi)); return r;
}
__device__ __forceinline__ void unpack2(float& lo, float& hi, ull v) {
    asm("mov.b64 {%0,%1}, %2;" : "=f"(lo), "=f"(hi) : "l"(v));
}
__device__ __forceinline__ void fma2(ull& acc, ull a, ull b) {
    asm("fma.rn.f32x2 %0, %1, %2, %0;" : "+l"(acc) : "l"(a), "l"(b));
}
__device__ __forceinline__ float tanh_ap(float x) {
    float y; asm("tanh.approx.f32 %0, %1;" : "=f"(y) : "f"(x)); return y;
}

// ---------------------------------------------------------------------------
// K12 fused: blocks [0,B1) compute xw = x@W_conv; blocks [B1,..) count degree
// ---------------------------------------------------------------------------
__global__ void k12_xw_deg(const float* __restrict__ x,
                           const float* __restrict__ Wc,
                           const int* __restrict__ colp,
                           int n, int e, int B1) {
    int tid = threadIdx.x;
    if ((int)blockIdx.x < B1) {
        __shared__ float4 sW[DIN * 4];
        if (tid < DIN * 4) sW[tid] = ((const float4*)Wc)[tid];
        __syncthreads();

        int i = blockIdx.x * blockDim.x + tid;
        if (i >= n) return;

        const float4* xr = (const float4*)(x + (size_t)i * DIN);
        float4 xv0 = xr[0], xv1 = xr[1], xv2 = xr[2], xv3 = xr[3];
        float xk[16] = {xv0.x, xv0.y, xv0.z, xv0.w,
                        xv1.x, xv1.y, xv1.z, xv1.w,
                        xv2.x, xv2.y, xv2.z, xv2.w,
                        xv3.x, xv3.y, xv3.z, xv3.w};

        float4 a0 = make_float4(0.f, 0.f, 0.f, 0.f);
        float4 a1 = a0, a2 = a0, a3 = a0;
#pragma unroll
        for (int k = 0; k < 16; k++) {
            float v = xk[k];
            float4 w0 = sW[k * 4 + 0], w1 = sW[k * 4 + 1];
            float4 w2 = sW[k * 4 + 2], w3 = sW[k * 4 + 3];
            a0.x += v * w0.x; a0.y += v * w0.y; a0.z += v * w0.z; a0.w += v * w0.w;
            a1.x += v * w1.x; a1.y += v * w1.y; a1.z += v * w1.z; a1.w += v * w1.w;
            a2.x += v * w2.x; a2.y += v * w2.y; a2.z += v * w2.z; a2.w += v * w2.w;
            a3.x += v * w3.x; a3.y += v * w3.y; a3.z += v * w3.z; a3.w += v * w3.w;
        }
        float4* dst = (float4*)(g_xw + (size_t)i * H);
        dst[0] = a0; dst[1] = a1; dst[2] = a2; dst[3] = a3;
    } else {
        int i = ((blockIdx.x - B1) * blockDim.x + tid) * 4;
        if (i >= e) return;
        if (i + 3 < e) {
            int4 v = __ldcs((const int4*)(colp + i));   // streaming: evict-first
            atomicAdd(&g_cnt[v.x], 1.0f);
            atomicAdd(&g_cnt[v.y], 1.0f);
            atomicAdd(&g_cnt[v.z], 1.0f);
            atomicAdd(&g_cnt[v.w], 1.0f);
        } else {
            for (int k = i; k < e; k++) atomicAdd(&g_cnt[colp[k]], 1.0f);
        }
    }
}

// ---------------------------------------------------------------------------
// K3: dis = rsqrt(1+cnt); cnt = 0; agg <- dis*xw (fp32 self-loop seed);
//     g_xwh <- dis*xw in fp16 (compact gather table for K4)
// ---------------------------------------------------------------------------
__global__ void k3_dis_scale(int n) {
    int i = blockIdx.x * blockDim.x + threadIdx.x;
    if (i >= n) return;
    float dis = rsqrtf(1.0f + g_cnt[i]);
    g_cnt[i] = 0.0f;
    g_dis[i] = dis;
    const float4* xr = (const float4*)(g_xw + (size_t)i * H);
    float4* ar = (float4*)(g_agg + (size_t)i * H);
    union { __half2 h[8]; uint4 u[2]; } tmp;
#pragma unroll
    for (int q = 0; q < 4; q++) {
        float4 v = xr[q];
        v.x *= dis; v.y *= dis; v.z *= dis; v.w *= dis;
        ar[q] = v;
        tmp.h[q * 2 + 0] = __floats2half2_rn(v.x, v.y);
        tmp.h[q * 2 + 1] = __floats2half2_rn(v.z, v.w);
    }
    uint4* hd = (uint4*)(g_xwh + (size_t)i * H);
    hd[0] = tmp.u[0];
    hd[1] = tmp.u[1];
}

// ---------------------------------------------------------------------------
// K4: agg[col] += xwh[row] — fp16 gather (32B/edge, L2-resident table),
//     fp32 vector RED. Streaming index loads (evict-first).
// ---------------------------------------------------------------------------
__device__ __forceinline__ void red_v4(float* dst, float4 v) {
    asm volatile("red.global.add.v4.f32 [%0], {%1,%2,%3,%4};"
                 :: "l"(dst), "f"(v.x), "f"(v.y), "f"(v.z), "f"(v.w)
                 : "memory");
}

__device__ __forceinline__ float4 cvt4(unsigned a, unsigned b) {
    float2 fa = __half22float2(*(const __half2*)&a);
    float2 fb = __half22float2(*(const __half2*)&b);
    return make_float4(fa.x, fa.y, fb.x, fb.y);
}

__device__ __forceinline__ void scatter_one(int r, int c) {
    const uint4* xh = (const uint4*)g_xwh + (size_t)r * 2;
    uint4 u0 = __ldg(xh);
    uint4 u1 = __ldg(xh + 1);
    float* dst = g_agg + (size_t)c * H;
    red_v4(dst + 0,  cvt4(u0.x, u0.y));
    red_v4(dst + 4,  cvt4(u0.z, u0.w));
    red_v4(dst + 8,  cvt4(u1.x, u1.y));
    red_v4(dst + 12, cvt4(u1.z, u1.w));
}

__global__ void k4_scatter(const int* __restrict__ rowp,
                           const int* __restrict__ colp, int e) {
    int i = (blockIdx.x * blockDim.x + threadIdx.x) * 4;
    if (i >= e) return;
    if (i + 3 < e) {
        int4 rv = __ldcs((const int4*)(rowp + i));
        int4 cv = __ldcs((const int4*)(colp + i));
        scatter_one(rv.x, cv.x);
        scatter_one(rv.y, cv.y);
        scatter_one(rv.z, cv.z);
        scatter_one(rv.w, cv.w);
    } else {
        for (int k = i; k < e; k++) scatter_one(rowp[k], colp[k]);
    }
}

// ---------------------------------------------------------------------------
// K5: x_emb = relu(dis*agg + b_conv); GRU; fc1+relu; fc2
//     Packed weights in SHARED (frees ~96 regs -> 6 blocks/SM).
//     tanh.approx MUFU for sigmoid/tanh.
// ---------------------------------------------------------------------------
__global__ void __launch_bounds__(256, 6)
k5_gru(const float* __restrict__ Zt, const int* __restrict__ firstp,
       const float* __restrict__ bconv,
       const float* __restrict__ Wir, const float* __restrict__ bir,
       const float* __restrict__ Whr, const float* __restrict__ bhr,
       const float* __restrict__ Wiz, const float* __restrict__ biz,
       const float* __restrict__ Whz, const float* __restrict__ bhz,
       const float* __restrict__ Win, const float* __restrict__ bin_,
       const float* __restrict__ Whn, const float* __restrict__ bhn,
       const float* __restrict__ Wf1, const float* __restrict__ bf1,
       const float* __restrict__ Wf2, const float* __restrict__ bf2,
       float* __restrict__ out_final, float* __restrict__ out_zbar, int n) {
    __shared__ ull    sPr[256], sPz[256], sPn[256];   // [k][j] packed (Wi, Wh)
    __shared__ float2 sAB[16][16];
    __shared__ float  sZ[16][16];
    __shared__ float  sHd[16][HIDN];
    __shared__ float  sWf1[16 * HIDN];
    __shared__ float  sWf2[HIDN * OUTN];

    int tid = threadIdx.x;
    int j = tid & 15;
    int nl = tid >> 4;

    // tid enumerates (k, j) pairs: row-major [k][j] matches weight layout
    sPr[tid] = pack2(Wir[tid], Whr[tid]);
    sPz[tid] = pack2(Wiz[tid], Whz[tid]);
    sPn[tid] = pack2(Win[tid], Whn[tid]);
    if (tid < 16 * HIDN) sWf1[tid] = Wf1[tid];
    if (tid < HIDN * OUTN) sWf2[tid] = Wf2[tid];

    float cb   = bconv[j];
    ull   br2  = pack2(bir[j] + bhr[j], 0.f);
    ull   bz2  = pack2(biz[j] + bhz[j], 0.f);
    ull   bn2  = pack2(bin_[j], bhn[j]);
    float bf1r = (j < HIDN) ? bf1[j] : 0.f;
    float bf2r = (j < OUTN) ? bf2[j] : 0.f;
    int first = firstp[0];
    __syncthreads();

    int ntiles = n >> 4;
    for (int t = blockIdx.x; t < ntiles; t += gridDim.x) {
        int base = t * 256;
        int node = t * 16 + nl;

        float dnode = __ldg(&g_dis[node]);
        float a = fmaf(dnode, __ldcs(&g_agg[base + tid]), cb);
        a = a > 0.f ? a : 0.f;
        float b = __ldcs(&Zt[base + tid]);
        sAB[nl][j] = make_float2(a, b);
        __syncwarp();

        ull r2 = br2, z2 = bz2, n2 = bn2;
        const ull* ab = (const ull*)sAB[nl];
#pragma unroll
        for (int k = 0; k < 16; k++) {
            ull t2 = ab[k];
            fma2(r2, t2, sPr[k * 16 + j]);
            fma2(z2, t2, sPz[k * 16 + j]);
            fma2(n2, t2, sPn[k * 16 + j]);
        }
        float rl, rh, zl, zh, nlv, nhv;
        unpack2(rl, rh, r2);
        unpack2(zl, zh, z2);
        unpack2(nlv, nhv, n2);
        float accr = rl + rh;
        float accz = zl + zh;

        float zb;
        if (first) {
            zb = a;
        } else {
            float r  = fmaf(tanh_ap(0.5f * accr), 0.5f, 0.5f);
            float z  = fmaf(tanh_ap(0.5f * accz), 0.5f, 0.5f);
            float nn = tanh_ap(fmaf(r, nhv, nlv));
            zb = (1.f - z) * nn + z * b;
        }
        out_zbar[base + tid] = zb;
        sZ[nl][j] = zb;
        __syncwarp();

        if (j < HIDN) {
            float h = bf1r;
#pragma unroll
            for (int k = 0; k < 16; k++)
                h += sZ[nl][k] * sWf1[k * HIDN + j];
            h = h > 0.f ? h : 0.f;
            sHd[nl][j] = h;
        }
        __syncwarp();

        if (j < OUTN) {
            float o = bf2r;
#pragma unroll
            for (int k = 0; k < HIDN; k++)
                o += sHd[nl][k] * sWf2[k * OUTN + j];
            out_final[node * OUTN + j] = o;
        }
        __syncwarp();
    }
}

// ---------------------------------------------------------------------------
// launch
// ---------------------------------------------------------------------------
extern "C" void kernel_launch(void* const* d_in, const int* in_sizes, int n_in,
                              void* d_out, int out_size) {
    const float* x      = (const float*)d_in[0];
    const int*   ei     = (const int*)d_in[1];
    const float* Zt     = (const float*)d_in[2];
    const int*   firstp = (const int*)d_in[3];
    const float* W_conv = (const float*)d_in[4];
    const float* b_conv = (const float*)d_in[5];
    const float* W_ir   = (const float*)d_in[6];
    const float* b_ir   = (const float*)d_in[7];
    const float* W_hr   = (const float*)d_in[8];
    const float* b_hr   = (const float*)d_in[9];
    const float* W_iz   = (const float*)d_in[10];
    const float* b_iz   = (const float*)d_in[11];
    const float* W_hz   = (const float*)d_in[12];
    const float* b_hz   = (const float*)d_in[13];
    const float* W_in   = (const float*)d_in[14];
    const float* b_in   = (const float*)d_in[15];
    const float* W_hn   = (const float*)d_in[16];
    const float* b_hn   = (const float*)d_in[17];
    const float* W_fc1  = (const float*)d_in[18];
    const float* b_fc1  = (const float*)d_in[19];
    const float* W_fc2  = (const float*)d_in[20];
    const float* b_fc2  = (const float*)d_in[21];

    const int n = in_sizes[0] / DIN;   // 1,000,000
    const int e = in_sizes[1] / 2;     // 16,000,000
    const int* rowp = ei;
    const int* colp = ei + e;

    float* out_final = (float*)d_out;
    float* out_zbar  = (float*)d_out + (size_t)n * OUTN;

    const int TPB = 256;
    const int B1 = (n + TPB - 1) / TPB;
    const int B2 = (e / 4 + TPB - 1) / TPB;

    k12_xw_deg<<<B1 + B2, TPB>>>(x, W_conv, colp, n, e, B1);
    k3_dis_scale<<<(n + TPB - 1) / TPB, TPB>>>(n);
    k4_scatter<<<(e / 4 + TPB - 1) / TPB, TPB>>>(rowp, colp, e);
    k5_gru<<<148 * 6, TPB>>>(Zt, firstp, b_conv,
                             W_ir, b_ir, W_hr, b_hr,
                             W_iz, b_iz, W_hz, b_hz,
                             W_in, b_in, W_hn, b_hn,
                             W_fc1, b_fc1, W_fc2, b_fc2,
                             out_final, out_zbar, n);
}

// round 6
// speedup vs baseline: 1.6164x; 1.3482x over previous
#include <cuda_runtime.h>
#include <cuda_fp16.h>
#include <math.h>

#define NN   1000000
#define EE   16000000
#define H    16
#define DIN  16
#define HIDN 8
#define OUTN 2
#define SCAN_BLK 1024            // elements per scan block (256 thr x 4)
#define NSB  ((NN + SCAN_BLK - 1) / SCAN_BLK)   // 977

typedef unsigned long long ull;

// Static device scratch. g_cnt starts 0 (module load); kscanC resets it to 0
// after consumption -> deterministic across graph replays.
__device__ float  g_xw[NN * H];     // x @ W_conv (fp32)
__device__ __half g_xwh[NN * H];    // dis[r]*xw[r] fp16 gather table (32MB)
__device__ float  g_agg[NN * H];    // gather output (fp32)
__device__ int    g_cnt[NN];        // in-degree histogram
__device__ float  g_dis[NN];        // rsqrt(1 + cnt)
__device__ int    g_off[NN + 1];    // CSR offsets (by col)
__device__ int    g_cur[NN];        // fill cursors
__device__ int    g_elist[EE];      // rows grouped by col
__device__ int    g_blk[1024];      // scan block sums

// ---------------------------------------------------------------------------
// packed f32x2 helpers
// ---------------------------------------------------------------------------
__device__ __forceinline__ ull pack2(float lo, float hi) {
    ull r; asm("mov.b64 %0, {%1,%2};" : "=l"(r) : "f"(lo), "f"(hi)); return r;
}
__device__ __forceinline__ void unpack2(float& lo, float& hi, ull v) {
    asm("mov.b64 {%0,%1}, %2;" : "=f"(lo), "=f"(hi) : "l"(v));
}
__device__ __forceinline__ void fma2(ull& acc, ull a, ull b) {
    asm("fma.rn.f32x2 %0, %1, %2, %0;" : "+l"(acc) : "l"(a), "l"(b));
}
__device__ __forceinline__ float tanh_ap(float x) {
    float y; asm("tanh.approx.f32 %0, %1;" : "=f"(y) : "f"(x)); return y;
}

// ---------------------------------------------------------------------------
// K12 fused: blocks [0,B1) -> xw = x@W_conv; blocks [B1,..) -> histogram
// ---------------------------------------------------------------------------
__global__ void k12_xw_deg(const float* __restrict__ x,
                           const float* __restrict__ Wc,
                           const int* __restrict__ colp,
                           int n, int e, int B1) {
    int tid = threadIdx.x;
    if ((int)blockIdx.x < B1) {
        __shared__ float4 sW[DIN * 4];
        if (tid < DIN * 4) sW[tid] = ((const float4*)Wc)[tid];
        __syncthreads();

        int i = blockIdx.x * blockDim.x + tid;
        if (i >= n) return;

        const float4* xr = (const float4*)(x + (size_t)i * DIN);
        float4 xv0 = xr[0], xv1 = xr[1], xv2 = xr[2], xv3 = xr[3];
        float xk[16] = {xv0.x, xv0.y, xv0.z, xv0.w,
                        xv1.x, xv1.y, xv1.z, xv1.w,
                        xv2.x, xv2.y, xv2.z, xv2.w,
                        xv3.x, xv3.y, xv3.z, xv3.w};

        float4 a0 = make_float4(0.f, 0.f, 0.f, 0.f);
        float4 a1 = a0, a2 = a0, a3 = a0;
#pragma unroll
        for (int k = 0; k < 16; k++) {
            float v = xk[k];
            float4 w0 = sW[k * 4 + 0], w1 = sW[k * 4 + 1];
            float4 w2 = sW[k * 4 + 2], w3 = sW[k * 4 + 3];
            a0.x += v * w0.x; a0.y += v * w0.y; a0.z += v * w0.z; a0.w += v * w0.w;
            a1.x += v * w1.x; a1.y += v * w1.y; a1.z += v * w1.z; a1.w += v * w1.w;
            a2.x += v * w2.x; a2.y += v * w2.y; a2.z += v * w2.z; a2.w += v * w2.w;
            a3.x += v * w3.x; a3.y += v * w3.y; a3.z += v * w3.z; a3.w += v * w3.w;
        }
        float4* dst = (float4*)(g_xw + (size_t)i * H);
        dst[0] = a0; dst[1] = a1; dst[2] = a2; dst[3] = a3;
    } else {
        int i = ((blockIdx.x - B1) * blockDim.x + tid) * 4;
        if (i >= e) return;
        if (i + 3 < e) {
            int4 v = __ldcs((const int4*)(colp + i));
            atomicAdd(&g_cnt[v.x], 1);
            atomicAdd(&g_cnt[v.y], 1);
            atomicAdd(&g_cnt[v.z], 1);
            atomicAdd(&g_cnt[v.w], 1);
        } else {
            for (int k = i; k < e; k++) atomicAdd(&g_cnt[colp[k]], 1);
        }
    }
}

// ---------------------------------------------------------------------------
// K3: dis = rsqrt(1+cnt); xwh = fp16(dis*xw). (cnt NOT reset here; scanC does)
// ---------------------------------------------------------------------------
__global__ void k3_dis(int n) {
    int i = blockIdx.x * blockDim.x + threadIdx.x;
    if (i >= n) return;
    float dis = rsqrtf(1.0f + (float)g_cnt[i]);
    g_dis[i] = dis;
    const float4* xr = (const float4*)(g_xw + (size_t)i * H);
    union { __half2 h[8]; uint4 u[2]; } tmp;
#pragma unroll
    for (int q = 0; q < 4; q++) {
        float4 v = xr[q];
        tmp.h[q * 2 + 0] = __floats2half2_rn(v.x * dis, v.y * dis);
        tmp.h[q * 2 + 1] = __floats2half2_rn(v.z * dis, v.w * dis);
    }
    uint4* hd = (uint4*)(g_xwh + (size_t)i * H);
    hd[0] = tmp.u[0];
    hd[1] = tmp.u[1];
}

// ---------------------------------------------------------------------------
// Scan A: per-block sums of g_cnt (1024 elems/block)
// ---------------------------------------------------------------------------
__global__ void kscanA(int n) {
    __shared__ int sm[256];
    int t = threadIdx.x, b = blockIdx.x;
    int idx = b * SCAN_BLK + t * 4;
    int s = 0;
    if (idx + 3 < n) {
        int4 v = *(const int4*)(g_cnt + idx);
        s = v.x + v.y + v.z + v.w;
    } else {
        for (int i = idx; i < n && i < idx + 4; i++) s += g_cnt[i];
    }
    sm[t] = s;
    __syncthreads();
#pragma unroll
    for (int o = 128; o > 0; o >>= 1) {
        if (t < o) sm[t] += sm[t + o];
        __syncthreads();
    }
    if (t == 0) g_blk[b] = sm[0];
}

// ---------------------------------------------------------------------------
// Scan B: exclusive scan of block sums (single block, Hillis-Steele)
// ---------------------------------------------------------------------------
__global__ void kscanB(int nb, int n, int e) {
    __shared__ int sm[1024];
    int t = threadIdx.x;
    int v = (t < nb) ? g_blk[t] : 0;
    sm[t] = v;
#pragma unroll
    for (int o = 1; o < 1024; o <<= 1) {
        __syncthreads();
        int x = (t >= o) ? sm[t - o] : 0;
        __syncthreads();
        sm[t] += x;
    }
    __syncthreads();
    if (t < nb) g_blk[t] = sm[t] - v;     // exclusive
    if (t == 0) g_off[n] = e;             // total is E by construction
}

// ---------------------------------------------------------------------------
// Scan C: local exclusive scan + block offset -> g_off, g_cur; reset g_cnt
// ---------------------------------------------------------------------------
__global__ void kscanC(int n) {
    __shared__ int sm[256];
    int t = threadIdx.x, b = blockIdx.x;
    int idx = b * SCAN_BLK + t * 4;
    int c0 = 0, c1 = 0, c2 = 0, c3 = 0;
    if (idx + 3 < n) {
        int4 v = *(const int4*)(g_cnt + idx);
        c0 = v.x; c1 = v.y; c2 = v.z; c3 = v.w;
    } else if (idx < n) {
        c0 = g_cnt[idx];
        if (idx + 1 < n) c1 = g_cnt[idx + 1];
        if (idx + 2 < n) c2 = g_cnt[idx + 2];
    }
    int ts = c0 + c1 + c2 + c3;
    sm[t] = ts;
#pragma unroll
    for (int o = 1; o < 256; o <<= 1) {
        __syncthreads();
        int x = (t >= o) ? sm[t - o] : 0;
        __syncthreads();
        sm[t] += x;
    }
    __syncthreads();
    int ex = g_blk[b] + sm[t] - ts;
    if (idx < n) {
        int o0 = ex, o1 = o0 + c0, o2 = o1 + c1, o3 = o2 + c2;
        g_off[idx] = o0; g_cur[idx] = o0; g_cnt[idx] = 0;
        if (idx + 1 < n) { g_off[idx + 1] = o1; g_cur[idx + 1] = o1; g_cnt[idx + 1] = 0; }
        if (idx + 2 < n) { g_off[idx + 2] = o2; g_cur[idx + 2] = o2; g_cnt[idx + 2] = 0; }
        if (idx + 3 < n) { g_off[idx + 3] = o3; g_cur[idx + 3] = o3; g_cnt[idx + 3] = 0; }
    }
}

// ---------------------------------------------------------------------------
// Reorder: elist grouped by col
// ---------------------------------------------------------------------------
__global__ void kreorder(const int* __restrict__ rowp,
                         const int* __restrict__ colp, int e) {
    int i = (blockIdx.x * blockDim.x + threadIdx.x) * 4;
    if (i >= e) return;
    if (i + 3 < e) {
        int4 r = __ldcs((const int4*)(rowp + i));
        int4 c = __ldcs((const int4*)(colp + i));
        g_elist[atomicAdd(&g_cur[c.x], 1)] = r.x;
        g_elist[atomicAdd(&g_cur[c.y], 1)] = r.y;
        g_elist[atomicAdd(&g_cur[c.z], 1)] = r.z;
        g_elist[atomicAdd(&g_cur[c.w], 1)] = r.w;
    } else {
        for (int k = i; k < e; k++)
            g_elist[atomicAdd(&g_cur[colp[k]], 1)] = rowp[k];
    }
}

// ---------------------------------------------------------------------------
// K4 gather: agg[c] = dis[c]*xw[c] + sum_{r in csr(c)} xwh[r]
//            2 threads/node (each owns 8 features = one 16B fp16 chunk)
// ---------------------------------------------------------------------------
__global__ void k4_gather(int n) {
    int tid = blockIdx.x * blockDim.x + threadIdx.x;
    int c = tid >> 1;
    if (c >= n) return;
    int half = tid & 1;

    int beg = __ldg(&g_off[c]);
    int end = __ldg(&g_off[c + 1]);
    float dis = __ldg(&g_dis[c]);

    const float4* xp = (const float4*)(g_xw + (size_t)c * H + half * 8);
    float4 A0 = xp[0], A1 = xp[1];
    A0.x *= dis; A0.y *= dis; A0.z *= dis; A0.w *= dis;
    A1.x *= dis; A1.y *= dis; A1.z *= dis; A1.w *= dis;

    int k = beg;
    for (; k + 1 < end; k += 2) {
        int r0 = __ldg(&g_elist[k]);
        int r1 = __ldg(&g_elist[k + 1]);
        uint4 u0 = __ldg((const uint4*)(g_xwh + (size_t)r0 * H + half * 8));
        uint4 u1 = __ldg((const uint4*)(g_xwh + (size_t)r1 * H + half * 8));
        float2 f;
        f = __half22float2(*(const __half2*)&u0.x); A0.x += f.x; A0.y += f.y;
        f = __half22float2(*(const __half2*)&u0.y); A0.z += f.x; A0.w += f.y;
        f = __half22float2(*(const __half2*)&u0.z); A1.x += f.x; A1.y += f.y;
        f = __half22float2(*(const __half2*)&u0.w); A1.z += f.x; A1.w += f.y;
        f = __half22float2(*(const __half2*)&u1.x); A0.x += f.x; A0.y += f.y;
        f = __half22float2(*(const __half2*)&u1.y); A0.z += f.x; A0.w += f.y;
        f = __half22float2(*(const __half2*)&u1.z); A1.x += f.x; A1.y += f.y;
        f = __half22float2(*(const __half2*)&u1.w); A1.z += f.x; A1.w += f.y;
    }
    if (k < end) {
        int r0 = __ldg(&g_elist[k]);
        uint4 u0 = __ldg((const uint4*)(g_xwh + (size_t)r0 * H + half * 8));
        float2 f;
        f = __half22float2(*(const __half2*)&u0.x); A0.x += f.x; A0.y += f.y;
        f = __half22float2(*(const __half2*)&u0.y); A0.z += f.x; A0.w += f.y;
        f = __half22float2(*(const __half2*)&u0.z); A1.x += f.x; A1.y += f.y;
        f = __half22float2(*(const __half2*)&u0.w); A1.z += f.x; A1.w += f.y;
    }

    float4* dst = (float4*)(g_agg + (size_t)c * H + half * 8);
    dst[0] = A0;
    dst[1] = A1;
}

// ---------------------------------------------------------------------------
// K5: relu(dis*agg+b) -> GRU -> fc1 -> fc2.  Warp owns 4 nodes; each thread
// computes 2 nodes per weight load (halves LDS pressure vs R5).
// ---------------------------------------------------------------------------
__global__ void __launch_bounds__(256, 6)
k5_gru(const float* __restrict__ Zt, const int* __restrict__ firstp,
       const float* __restrict__ bconv,
       const float* __restrict__ Wir, const float* __restrict__ bir,
       const float* __restrict__ Whr, const float* __restrict__ bhr,
       const float* __restrict__ Wiz, const float* __restrict__ biz,
       const float* __restrict__ Whz, const float* __restrict__ bhz,
       const float* __restrict__ Win, const float* __restrict__ bin_,
       const float* __restrict__ Whn, const float* __restrict__ bhn,
       const float* __restrict__ Wf1, const float* __restrict__ bf1,
       const float* __restrict__ Wf2, const float* __restrict__ bf2,
       float* __restrict__ out_final, float* __restrict__ out_zbar, int n) {
    __shared__ ull    sPr[256], sPz[256], sPn[256];
    __shared__ float2 sAB[32][16];
    __shared__ float  sZ[32][16];
    __shared__ float  sHd[32][HIDN];
    __shared__ float  sWf1[16 * HIDN];
    __shared__ float  sWf2[HIDN * OUTN];
    __shared__ float  sCb[16];

    int tid  = threadIdx.x;
    int lane = tid & 31;
    int w    = tid >> 5;       // warp 0..7
    int j    = lane & 15;      // output feature
    int q    = lane >> 4;      // node pair within warp
    int n0l  = (w << 2) + (q << 1);   // local node ids (0..31)
    int n1l  = n0l + 1;

    sPr[tid] = pack2(Wir[tid], Whr[tid]);
    sPz[tid] = pack2(Wiz[tid], Whz[tid]);
    sPn[tid] = pack2(Win[tid], Whn[tid]);
    if (tid < 16 * HIDN) sWf1[tid] = Wf1[tid];
    if (tid < HIDN * OUTN) sWf2[tid] = Wf2[tid];
    if (tid < 16) sCb[tid] = bconv[tid];

    ull   br2  = pack2(bir[j] + bhr[j], 0.f);
    ull   bz2  = pack2(biz[j] + bhz[j], 0.f);
    ull   bn2  = pack2(bin_[j], bhn[j]);
    float bf1r = bf1[j & (HIDN - 1)];
    float bf2r = bf2[j & (OUTN - 1)];
    int first = firstp[0];
    __syncthreads();

    int ntiles = n >> 5;   // 32 nodes per tile
    for (int t = blockIdx.x; t < ntiles; t += gridDim.x) {
        int base = t * 512;  // floats

        // Loader: warp w fills sAB rows [4w, 4w+4) (64 elements, 2 rounds)
#pragma unroll
        for (int m = 0; m < 2; m++) {
            int fl = (w << 6) + (m << 5) + lane;    // local flat 0..511
            int nloc = fl >> 4;
            int k = fl & 15;
            float dis = __ldg(&g_dis[t * 32 + nloc]);
            float a = fmaf(dis, __ldcs(&g_agg[base + fl]), sCb[k]);
            a = a > 0.f ? a : 0.f;
            float b = __ldcs(&Zt[base + fl]);
            sAB[nloc][k] = make_float2(a, b);
        }
        __syncwarp();

        // Gates for two nodes, shared weight loads
        ull r20 = br2, z20 = bz2, n20 = bn2;
        ull r21 = br2, z21 = bz2, n21 = bn2;
        const ull* ab0 = (const ull*)sAB[n0l];
        const ull* ab1 = (const ull*)sAB[n1l];
#pragma unroll
        for (int k = 0; k < 16; k++) {
            ull wr = sPr[k * 16 + j];
            ull wz = sPz[k * 16 + j];
            ull wn = sPn[k * 16 + j];
            ull t0 = ab0[k];
            ull t1 = ab1[k];
            fma2(r20, t0, wr); fma2(r21, t1, wr);
            fma2(z20, t0, wz); fma2(z21, t1, wz);
            fma2(n20, t0, wn); fma2(n21, t1, wn);
        }

        float zb0, zb1;
        {
            float rl, rh, zl, zh, nlv, nhv;
            unpack2(rl, rh, r20); unpack2(zl, zh, z20); unpack2(nlv, nhv, n20);
            float a0 = sAB[n0l][j].x, b0 = sAB[n0l][j].y;
            if (first) zb0 = a0;
            else {
                float r  = fmaf(tanh_ap(0.5f * (rl + rh)), 0.5f, 0.5f);
                float z  = fmaf(tanh_ap(0.5f * (zl + zh)), 0.5f, 0.5f);
                float nn = tanh_ap(fmaf(r, nhv, nlv));
                zb0 = (1.f - z) * nn + z * b0;
            }
            unpack2(rl, rh, r21); unpack2(zl, zh, z21); unpack2(nlv, nhv, n21);
            float a1 = sAB[n1l][j].x, b1 = sAB[n1l][j].y;
            if (first) zb1 = a1;
            else {
                float r  = fmaf(tanh_ap(0.5f * (rl + rh)), 0.5f, 0.5f);
                float z  = fmaf(tanh_ap(0.5f * (zl + zh)), 0.5f, 0.5f);
                float nn = tanh_ap(fmaf(r, nhv, nlv));
                zb1 = (1.f - z) * nn + z * b1;
            }
        }
        out_zbar[base + n0l * 16 + j] = zb0;
        out_zbar[base + n1l * 16 + j] = zb1;
        sZ[n0l][j] = zb0;
        sZ[n1l][j] = zb1;
        __syncwarp();

        // FC1: 4 nodes x 8 hidden = 32 lanes
        {
            int nloc = (w << 2) + (lane >> 3);
            int jj = lane & 7;
            float h = bf1r;  // careful: bf1r is bf1[j&7]; need bf1[jj]
            // recompute correct bias from shared-free constant: use sWf1-free path
            h = 0.f;
#pragma unroll
            for (int k = 0; k < 16; k++)
                h += sZ[nloc][k] * sWf1[k * HIDN + jj];
            h += __ldg(&bf1[jj]);
            h = h > 0.f ? h : 0.f;
            sHd[nloc][jj] = h;
        }
        __syncwarp();

        // FC2: 4 nodes x 2 outputs = 8 lanes
        if (lane < 8) {
            int nloc = (w << 2) + (lane >> 1);
            int jj = lane & 1;
            float o = __ldg(&bf2[jj]);
#pragma unroll
            for (int k = 0; k < HIDN; k++)
                o += sHd[nloc][k] * sWf2[k * OUTN + jj];
            out_final[(t * 32 + nloc) * OUTN + jj] = o;
        }
        __syncwarp();
    }
}

// ---------------------------------------------------------------------------
// launch
// ---------------------------------------------------------------------------
extern "C" void kernel_launch(void* const* d_in, const int* in_sizes, int n_in,
                              void* d_out, int out_size) {
    const float* x      = (const float*)d_in[0];
    const int*   ei     = (const int*)d_in[1];
    const float* Zt     = (const float*)d_in[2];
    const int*   firstp = (const int*)d_in[3];
    const float* W_conv = (const float*)d_in[4];
    const float* b_conv = (const float*)d_in[5];
    const float* W_ir   = (const float*)d_in[6];
    const float* b_ir   = (const float*)d_in[7];
    const float* W_hr   = (const float*)d_in[8];
    const float* b_hr   = (const float*)d_in[9];
    const float* W_iz   = (const float*)d_in[10];
    const float* b_iz   = (const float*)d_in[11];
    const float* W_hz   = (const float*)d_in[12];
    const float* b_hz   = (const float*)d_in[13];
    const float* W_in   = (const float*)d_in[14];
    const float* b_in   = (const float*)d_in[15];
    const float* W_hn   = (const float*)d_in[16];
    const float* b_hn   = (const float*)d_in[17];
    const float* W_fc1  = (const float*)d_in[18];
    const float* b_fc1  = (const float*)d_in[19];
    const float* W_fc2  = (const float*)d_in[20];
    const float* b_fc2  = (const float*)d_in[21];

    const int n = in_sizes[0] / DIN;   // 1,000,000
    const int e = in_sizes[1] / 2;     // 16,000,000
    const int* rowp = ei;
    const int* colp = ei + e;

    float* out_final = (float*)d_out;
    float* out_zbar  = (float*)d_out + (size_t)n * OUTN;

    const int TPB = 256;
    const int B1 = (n + TPB - 1) / TPB;
    const int B2 = (e / 4 + TPB - 1) / TPB;
    const int nsb = (n + SCAN_BLK - 1) / SCAN_BLK;

    k12_xw_deg<<<B1 + B2, TPB>>>(x, W_conv, colp, n, e, B1);
    k3_dis<<<(n + TPB - 1) / TPB, TPB>>>(n);
    kscanA<<<nsb, 256>>>(n);
    kscanB<<<1, 1024>>>(nsb, n, e);
    kscanC<<<nsb, 256>>>(n);
    kreorder<<<(e / 4 + TPB - 1) / TPB, TPB>>>(rowp, colp, e);
    k4_gather<<<(2 * n + TPB - 1) / TPB, TPB>>>(n);
    k5_gru<<<148 * 6, TPB>>>(Zt, firstp, b_conv,
                             W_ir, b_ir, W_hr, b_hr,
                             W_iz, b_iz, W_hz, b_hz,
                             W_in, b_in, W_hn, b_hn,
                             W_fc1, b_fc1, W_fc2, b_fc2,
                             out_final, out_zbar, n);
}

// round 7
// speedup vs baseline: 2.0678x; 1.2793x over previous
#include <cuda_runtime.h>
#include <cuda_fp16.h>
#include <math.h>

#define NN   1000000
#define EE   16000000
#define H    16
#define DIN  16
#define HIDN 8
#define OUTN 2
#define SCAN_BLK 1024

typedef unsigned long long ull;
typedef unsigned int uint;

// Static device scratch. g_cnt starts 0 (module load); kscanC resets it to 0
// after consumption -> deterministic across graph replays.
__device__ float  g_xw[NN * H];
__device__ __half g_xwh[NN * H];
__device__ float  g_agg[NN * H];
__device__ int    g_cnt[NN];
__device__ float  g_dis[NN];
__device__ int    g_off[NN + 1];
__device__ int    g_cur[NN];
__device__ int    g_elist[EE];
__device__ int    g_blk[1024];

__device__ __forceinline__ float tanh_ap(float x) {
    float y; asm("tanh.approx.f32 %0, %1;" : "=f"(y) : "f"(x)); return y;
}
__device__ __forceinline__ uint packh2(float x, float y) {
    __half2 h = __floats2half2_rn(x, y);
    return *(uint*)&h;
}
__device__ __forceinline__ float2 unpackh2(uint v) {
    return __half22float2(*(__half2*)&v);
}
__device__ __forceinline__ void mma16816(float* c, const uint* a, uint b0, uint b1) {
    asm("mma.sync.aligned.m16n8k16.row.col.f32.f16.f16.f32 "
        "{%0,%1,%2,%3},{%4,%5,%6,%7},{%8,%9},{%0,%1,%2,%3};"
        : "+f"(c[0]), "+f"(c[1]), "+f"(c[2]), "+f"(c[3])
        : "r"(a[0]), "r"(a[1]), "r"(a[2]), "r"(a[3]), "r"(b0), "r"(b1));
}

// ---------------------------------------------------------------------------
// K12 fused: blocks [0,B1) -> xw = x@W_conv; blocks [B1,..) -> histogram
// ---------------------------------------------------------------------------
__global__ void k12_xw_deg(const float* __restrict__ x,
                           const float* __restrict__ Wc,
                           const int* __restrict__ colp,
                           int n, int e, int B1) {
    int tid = threadIdx.x;
    if ((int)blockIdx.x < B1) {
        __shared__ float4 sW[DIN * 4];
        if (tid < DIN * 4) sW[tid] = ((const float4*)Wc)[tid];
        __syncthreads();

        int i = blockIdx.x * blockDim.x + tid;
        if (i >= n) return;

        const float4* xr = (const float4*)(x + (size_t)i * DIN);
        float4 xv0 = xr[0], xv1 = xr[1], xv2 = xr[2], xv3 = xr[3];
        float xk[16] = {xv0.x, xv0.y, xv0.z, xv0.w,
                        xv1.x, xv1.y, xv1.z, xv1.w,
                        xv2.x, xv2.y, xv2.z, xv2.w,
                        xv3.x, xv3.y, xv3.z, xv3.w};

        float4 a0 = make_float4(0.f, 0.f, 0.f, 0.f);
        float4 a1 = a0, a2 = a0, a3 = a0;
#pragma unroll
        for (int k = 0; k < 16; k++) {
            float v = xk[k];
            float4 w0 = sW[k * 4 + 0], w1 = sW[k * 4 + 1];
            float4 w2 = sW[k * 4 + 2], w3 = sW[k * 4 + 3];
            a0.x += v * w0.x; a0.y += v * w0.y; a0.z += v * w0.z; a0.w += v * w0.w;
            a1.x += v * w1.x; a1.y += v * w1.y; a1.z += v * w1.z; a1.w += v * w1.w;
            a2.x += v * w2.x; a2.y += v * w2.y; a2.z += v * w2.z; a2.w += v * w2.w;
            a3.x += v * w3.x; a3.y += v * w3.y; a3.z += v * w3.z; a3.w += v * w3.w;
        }
        float4* dst = (float4*)(g_xw + (size_t)i * H);
        dst[0] = a0; dst[1] = a1; dst[2] = a2; dst[3] = a3;
    } else {
        int i = ((blockIdx.x - B1) * blockDim.x + tid) * 4;
        if (i >= e) return;
        if (i + 3 < e) {
            int4 v = __ldcs((const int4*)(colp + i));
            atomicAdd(&g_cnt[v.x], 1);
            atomicAdd(&g_cnt[v.y], 1);
            atomicAdd(&g_cnt[v.z], 1);
            atomicAdd(&g_cnt[v.w], 1);
        } else {
            for (int k = i; k < e; k++) atomicAdd(&g_cnt[colp[k]], 1);
        }
    }
}

// ---------------------------------------------------------------------------
// K3: dis = rsqrt(1+cnt); xwh = fp16(dis*xw)
// ---------------------------------------------------------------------------
__global__ void k3_dis(int n) {
    int i = blockIdx.x * blockDim.x + threadIdx.x;
    if (i >= n) return;
    float dis = rsqrtf(1.0f + (float)g_cnt[i]);
    g_dis[i] = dis;
    const float4* xr = (const float4*)(g_xw + (size_t)i * H);
    union { __half2 h[8]; uint4 u[2]; } tmp;
#pragma unroll
    for (int q = 0; q < 4; q++) {
        float4 v = xr[q];
        tmp.h[q * 2 + 0] = __floats2half2_rn(v.x * dis, v.y * dis);
        tmp.h[q * 2 + 1] = __floats2half2_rn(v.z * dis, v.w * dis);
    }
    uint4* hd = (uint4*)(g_xwh + (size_t)i * H);
    hd[0] = tmp.u[0];
    hd[1] = tmp.u[1];
}

// ---------------------------------------------------------------------------
// Scans -> CSR offsets
// ---------------------------------------------------------------------------
__global__ void kscanA(int n) {
    __shared__ int sm[256];
    int t = threadIdx.x, b = blockIdx.x;
    int idx = b * SCAN_BLK + t * 4;
    int s = 0;
    if (idx + 3 < n) {
        int4 v = *(const int4*)(g_cnt + idx);
        s = v.x + v.y + v.z + v.w;
    } else {
        for (int i = idx; i < n && i < idx + 4; i++) s += g_cnt[i];
    }
    sm[t] = s;
    __syncthreads();
#pragma unroll
    for (int o = 128; o > 0; o >>= 1) {
        if (t < o) sm[t] += sm[t + o];
        __syncthreads();
    }
    if (t == 0) g_blk[b] = sm[0];
}

__global__ void kscanB(int nb, int n, int e) {
    __shared__ int sm[1024];
    int t = threadIdx.x;
    int v = (t < nb) ? g_blk[t] : 0;
    sm[t] = v;
#pragma unroll
    for (int o = 1; o < 1024; o <<= 1) {
        __syncthreads();
        int x = (t >= o) ? sm[t - o] : 0;
        __syncthreads();
        sm[t] += x;
    }
    __syncthreads();
    if (t < nb) g_blk[t] = sm[t] - v;
    if (t == 0) g_off[n] = e;
}

__global__ void kscanC(int n) {
    __shared__ int sm[256];
    int t = threadIdx.x, b = blockIdx.x;
    int idx = b * SCAN_BLK + t * 4;
    int c0 = 0, c1 = 0, c2 = 0, c3 = 0;
    if (idx + 3 < n) {
        int4 v = *(const int4*)(g_cnt + idx);
        c0 = v.x; c1 = v.y; c2 = v.z; c3 = v.w;
    } else if (idx < n) {
        c0 = g_cnt[idx];
        if (idx + 1 < n) c1 = g_cnt[idx + 1];
        if (idx + 2 < n) c2 = g_cnt[idx + 2];
    }
    int ts = c0 + c1 + c2 + c3;
    sm[t] = ts;
#pragma unroll
    for (int o = 1; o < 256; o <<= 1) {
        __syncthreads();
        int x = (t >= o) ? sm[t - o] : 0;
        __syncthreads();
        sm[t] += x;
    }
    __syncthreads();
    int ex = g_blk[b] + sm[t] - ts;
    if (idx < n) {
        int o0 = ex, o1 = o0 + c0, o2 = o1 + c1, o3 = o2 + c2;
        g_off[idx] = o0; g_cur[idx] = o0; g_cnt[idx] = 0;
        if (idx + 1 < n) { g_off[idx + 1] = o1; g_cur[idx + 1] = o1; g_cnt[idx + 1] = 0; }
        if (idx + 2 < n) { g_off[idx + 2] = o2; g_cur[idx + 2] = o2; g_cnt[idx + 2] = 0; }
        if (idx + 3 < n) { g_off[idx + 3] = o3; g_cur[idx + 3] = o3; g_cnt[idx + 3] = 0; }
    }
}

__global__ void kreorder(const int* __restrict__ rowp,
                         const int* __restrict__ colp, int e) {
    int i = (blockIdx.x * blockDim.x + threadIdx.x) * 4;
    if (i >= e) return;
    if (i + 3 < e) {
        int4 r = __ldcs((const int4*)(rowp + i));
        int4 c = __ldcs((const int4*)(colp + i));
        g_elist[atomicAdd(&g_cur[c.x], 1)] = r.x;
        g_elist[atomicAdd(&g_cur[c.y], 1)] = r.y;
        g_elist[atomicAdd(&g_cur[c.z], 1)] = r.z;
        g_elist[atomicAdd(&g_cur[c.w], 1)] = r.w;
    } else {
        for (int k = i; k < e; k++)
            g_elist[atomicAdd(&g_cur[colp[k]], 1)] = rowp[k];
    }
}

// ---------------------------------------------------------------------------
// K4 gather: grid-stride over 2N half-rows for load balance
// ---------------------------------------------------------------------------
__global__ void k4_gather(int n2) {
    int stride = gridDim.x * blockDim.x;
    for (int tid = blockIdx.x * blockDim.x + threadIdx.x; tid < n2; tid += stride) {
        int c = tid >> 1;
        int half = tid & 1;

        int beg = __ldg(&g_off[c]);
        int end = __ldg(&g_off[c + 1]);
        float dis = __ldg(&g_dis[c]);

        const float4* xp = (const float4*)(g_xw + (size_t)c * H + half * 8);
        float4 A0 = xp[0], A1 = xp[1];
        A0.x *= dis; A0.y *= dis; A0.z *= dis; A0.w *= dis;
        A1.x *= dis; A1.y *= dis; A1.z *= dis; A1.w *= dis;

        int k = beg;
        for (; k + 1 < end; k += 2) {
            int r0 = __ldg(&g_elist[k]);
            int r1 = __ldg(&g_elist[k + 1]);
            uint4 u0 = __ldg((const uint4*)(g_xwh + (size_t)r0 * H + half * 8));
            uint4 u1 = __ldg((const uint4*)(g_xwh + (size_t)r1 * H + half * 8));
            float2 f;
            f = __half22float2(*(const __half2*)&u0.x); A0.x += f.x; A0.y += f.y;
            f = __half22float2(*(const __half2*)&u0.y); A0.z += f.x; A0.w += f.y;
            f = __half22float2(*(const __half2*)&u0.z); A1.x += f.x; A1.y += f.y;
            f = __half22float2(*(const __half2*)&u0.w); A1.z += f.x; A1.w += f.y;
            f = __half22float2(*(const __half2*)&u1.x); A0.x += f.x; A0.y += f.y;
            f = __half22float2(*(const __half2*)&u1.y); A0.z += f.x; A0.w += f.y;
            f = __half22float2(*(const __half2*)&u1.z); A1.x += f.x; A1.y += f.y;
            f = __half22float2(*(const __half2*)&u1.w); A1.z += f.x; A1.w += f.y;
        }
        if (k < end) {
            int r0 = __ldg(&g_elist[k]);
            uint4 u0 = __ldg((const uint4*)(g_xwh + (size_t)r0 * H + half * 8));
            float2 f;
            f = __half22float2(*(const __half2*)&u0.x); A0.x += f.x; A0.y += f.y;
            f = __half22float2(*(const __half2*)&u0.y); A0.z += f.x; A0.w += f.y;
            f = __half22float2(*(const __half2*)&u0.z); A1.x += f.x; A1.y += f.y;
            f = __half22float2(*(const __half2*)&u0.w); A1.z += f.x; A1.w += f.y;
        }

        float4* dst = (float4*)(g_agg + (size_t)c * H + half * 8);
        dst[0] = A0;
        dst[1] = A1;
    }
}

// ---------------------------------------------------------------------------
// K5 (HMMA): per warp, tile of 16 nodes.
//   Gates: [16x32]@[32x64] via 16x mma.m16n8k16 (A cols: a|b; B rows: Wi|Wh;
//          B col blocks: r, z, ni, nh).  B-frags constant in registers.
//   GRU elementwise fully thread-local; FC1 = 1 HMMA; FC2 = shfl reduction.
// ---------------------------------------------------------------------------
__global__ void __launch_bounds__(128, 4)
k5_gru(const float* __restrict__ Zt, const int* __restrict__ firstp,
       const float* __restrict__ bconv,
       const float* __restrict__ Wir, const float* __restrict__ bir,
       const float* __restrict__ Whr, const float* __restrict__ bhr,
       const float* __restrict__ Wiz, const float* __restrict__ biz,
       const float* __restrict__ Whz, const float* __restrict__ bhz,
       const float* __restrict__ Win, const float* __restrict__ bin_,
       const float* __restrict__ Whn, const float* __restrict__ bhn,
       const float* __restrict__ Wf1, const float* __restrict__ bf1,
       const float* __restrict__ Wf2, const float* __restrict__ bf2,
       float* __restrict__ out_final, float* __restrict__ out_zbar, int n) {
    __shared__ float sZ[4][256];   // per-warp zbar staging [m][j]

    int lane = threadIdx.x & 31;
    int w    = threadIdx.x >> 5;
    int g    = lane >> 2;          // 0..7
    int t    = lane & 3;           // 0..3
    int t2   = t * 2;

    // ---- constant B fragments for the gate MMA (nt 0..7, ks 0..1) ----
    // gate blocks: nt 0-1: r, 2-3: z, 4-5: ni, 6-7: nh
    uint bf[16][2];
#pragma unroll
    for (int nt = 0; nt < 8; nt++) {
        int gate = nt >> 1;
        int j = ((nt & 1) << 3) + g;     // col within gate block
        const float* Wi = (gate == 0) ? Wir : (gate == 1) ? Wiz : (gate == 2) ? Win : 0;
        const float* Wh = (gate == 0) ? Whr : (gate == 1) ? Whz : (gate == 3) ? Whn : 0;
#pragma unroll
        for (int ks = 0; ks < 2; ks++) {
            const float* W = ks ? Wh : Wi;
            float w0 = W ? W[(t2) * 16 + j]     : 0.f;
            float w1 = W ? W[(t2 + 1) * 16 + j] : 0.f;
            float w2 = W ? W[(t2 + 8) * 16 + j] : 0.f;
            float w3 = W ? W[(t2 + 9) * 16 + j] : 0.f;
            bf[nt * 2 + ks][0] = packh2(w0, w1);
            bf[nt * 2 + ks][1] = packh2(w2, w3);
        }
    }
    // gate biases for D cols (nt, t2) and (nt, t2+1)
    float bias0[8], bias1[8];
#pragma unroll
    for (int nt = 0; nt < 8; nt++) {
        int gate = nt >> 1;
        int j0 = ((nt & 1) << 3) + t2;
        int j1 = j0 + 1;
        if (gate == 0)      { bias0[nt] = bir[j0] + bhr[j0]; bias1[nt] = bir[j1] + bhr[j1]; }
        else if (gate == 1) { bias0[nt] = biz[j0] + bhz[j0]; bias1[nt] = biz[j1] + bhz[j1]; }
        else if (gate == 2) { bias0[nt] = bin_[j0];          bias1[nt] = bin_[j1]; }
        else                { bias0[nt] = bhn[j0];           bias1[nt] = bhn[j1]; }
    }
    float cb0 = bconv[t2], cb1 = bconv[t2 + 1], cb2 = bconv[t2 + 8], cb3 = bconv[t2 + 9];
    // FC1 fragment (Wf1 [16x8], col g), bias for D cols t2, t2+1
    uint wf1f0 = packh2(Wf1[t2 * 8 + g],       Wf1[(t2 + 1) * 8 + g]);
    uint wf1f1 = packh2(Wf1[(t2 + 8) * 8 + g], Wf1[(t2 + 9) * 8 + g]);
    float bf1c0 = bf1[t2 & 7], bf1c1 = bf1[(t2 + 1) & 7];
    // FC2 weights for rows t2, t2+1
    float w2a = Wf2[t2 * 2 + 0], w2b = Wf2[t2 * 2 + 1];
    float w2c = Wf2[(t2 + 1) * 2 + 0], w2d = Wf2[(t2 + 1) * 2 + 1];
    float b20 = bf2[0], b21 = bf2[1];
    int first = firstp[0];

    int gwarp  = (blockIdx.x * blockDim.x + threadIdx.x) >> 5;
    int nwarps = (gridDim.x * blockDim.x) >> 5;
    int ntiles = n >> 4;

    for (int tile = gwarp; tile < ntiles; tile += nwarps) {
        int tb = tile << 4;
        int n0 = tb + g, n1 = n0 + 8;

        float dis0 = __ldg(&g_dis[n0]);
        float dis1 = __ldg(&g_dis[n1]);

        const float2* ag0 = (const float2*)(g_agg + (size_t)n0 * 16);
        const float2* ag1 = (const float2*)(g_agg + (size_t)n1 * 16);
        float2 q00 = __ldcs(ag0 + t), q01 = __ldcs(ag0 + 4 + t);
        float2 q10 = __ldcs(ag1 + t), q11 = __ldcs(ag1 + 4 + t);
        const float2* zt0 = (const float2*)(Zt + (size_t)n0 * 16);
        const float2* zt1 = (const float2*)(Zt + (size_t)n1 * 16);
        float2 z00 = __ldcs(zt0 + t), z01 = __ldcs(zt0 + 4 + t);
        float2 z10 = __ldcs(zt1 + t), z11 = __ldcs(zt1 + 4 + t);

        float a00x = fmaf(dis0, q00.x, cb0); a00x = a00x > 0.f ? a00x : 0.f;
        float a00y = fmaf(dis0, q00.y, cb1); a00y = a00y > 0.f ? a00y : 0.f;
        float a10x = fmaf(dis1, q10.x, cb0); a10x = a10x > 0.f ? a10x : 0.f;
        float a10y = fmaf(dis1, q10.y, cb1); a10y = a10y > 0.f ? a10y : 0.f;
        float a01x = fmaf(dis0, q01.x, cb2); a01x = a01x > 0.f ? a01x : 0.f;
        float a01y = fmaf(dis0, q01.y, cb3); a01y = a01y > 0.f ? a01y : 0.f;
        float a11x = fmaf(dis1, q11.x, cb2); a11x = a11x > 0.f ? a11x : 0.f;
        float a11y = fmaf(dis1, q11.y, cb3); a11y = a11y > 0.f ? a11y : 0.f;

        uint afA[4], afB[4];
        afA[0] = packh2(a00x, a00y); afA[1] = packh2(a10x, a10y);
        afA[2] = packh2(a01x, a01y); afA[3] = packh2(a11x, a11y);
        afB[0] = packh2(z00.x, z00.y); afB[1] = packh2(z10.x, z10.y);
        afB[2] = packh2(z01.x, z01.y); afB[3] = packh2(z11.x, z11.y);

        float acc[32];
#pragma unroll
        for (int nt = 0; nt < 8; nt++) {
            acc[nt * 4 + 0] = bias0[nt]; acc[nt * 4 + 1] = bias1[nt];
            acc[nt * 4 + 2] = bias0[nt]; acc[nt * 4 + 3] = bias1[nt];
        }
#pragma unroll
        for (int nt = 0; nt < 8; nt++) {
            mma16816(acc + nt * 4, afA, bf[nt * 2 + 0][0], bf[nt * 2 + 0][1]);
            mma16816(acc + nt * 4, afB, bf[nt * 2 + 1][0], bf[nt * 2 + 1][1]);
        }

        // elementwise GRU for 4 (row, colpair) fragments
        uint zfrag[4];
#pragma unroll
        for (int f = 0; f < 4; f++) {
            int ntoff = f >> 1;          // 0: cols t2.. ; 1: cols 8+t2..
            int cp = (f & 1) * 2;        // 0: row g ; 2: row g+8
            float r0 = acc[(0 + ntoff) * 4 + cp], r1 = acc[(0 + ntoff) * 4 + cp + 1];
            float zz0 = acc[(2 + ntoff) * 4 + cp], zz1 = acc[(2 + ntoff) * 4 + cp + 1];
            float ni0 = acc[(4 + ntoff) * 4 + cp], ni1 = acc[(4 + ntoff) * 4 + cp + 1];
            float nh0 = acc[(6 + ntoff) * 4 + cp], nh1 = acc[(6 + ntoff) * 4 + cp + 1];
            float2 av = unpackh2(afA[f]);
            float2 bv = unpackh2(afB[f]);
            float zb0, zb1;
            if (first) {
                zb0 = av.x; zb1 = av.y;
            } else {
                float rr0 = fmaf(tanh_ap(0.5f * r0), 0.5f, 0.5f);
                float rr1 = fmaf(tanh_ap(0.5f * r1), 0.5f, 0.5f);
                float zg0 = fmaf(tanh_ap(0.5f * zz0), 0.5f, 0.5f);
                float zg1 = fmaf(tanh_ap(0.5f * zz1), 0.5f, 0.5f);
                float nn0 = tanh_ap(fmaf(rr0, nh0, ni0));
                float nn1 = tanh_ap(fmaf(rr1, nh1, ni1));
                zb0 = (1.f - zg0) * nn0 + zg0 * bv.x;
                zb1 = (1.f - zg1) * nn1 + zg1 * bv.y;
            }
            zfrag[f] = packh2(zb0, zb1);
            int row = (f & 1) ? g + 8 : g;
            int col = (f >> 1) ? 8 + t2 : t2;
            *(float2*)&sZ[w][row * 16 + col] = make_float2(zb0, zb1);
        }

        // FC1 via HMMA: Z[16x16] @ Wf1[16x8]
        float h[4] = {bf1c0, bf1c1, bf1c0, bf1c1};
        mma16816(h, zfrag, wf1f0, wf1f1);
        h[0] = h[0] > 0.f ? h[0] : 0.f;
        h[1] = h[1] > 0.f ? h[1] : 0.f;
        h[2] = h[2] > 0.f ? h[2] : 0.f;
        h[3] = h[3] > 0.f ? h[3] : 0.f;

        // FC2: partials over this thread's 2 hidden cols, reduce over 4 lanes
        float p00 = h[0] * w2a + h[1] * w2c;
        float p01 = h[0] * w2b + h[1] * w2d;
        float p10 = h[2] * w2a + h[3] * w2c;
        float p11 = h[2] * w2b + h[3] * w2d;
#pragma unroll
        for (int m = 1; m <= 2; m <<= 1) {
            p00 += __shfl_xor_sync(0xffffffffu, p00, m);
            p01 += __shfl_xor_sync(0xffffffffu, p01, m);
            p10 += __shfl_xor_sync(0xffffffffu, p10, m);
            p11 += __shfl_xor_sync(0xffffffffu, p11, m);
        }
        if (t == 0) {
            *(float2*)(out_final + (size_t)n0 * 2) = make_float2(p00 + b20, p01 + b21);
            *(float2*)(out_final + (size_t)n1 * 2) = make_float2(p10 + b20, p11 + b21);
        }

        // coalesced zbar store
        __syncwarp();
        const float4* src = (const float4*)sZ[w];
        float4* dst = (float4*)(out_zbar + (size_t)tb * 16);
        dst[lane]      = src[lane];
        dst[lane + 32] = src[lane + 32];
        __syncwarp();
    }
}

// ---------------------------------------------------------------------------
// launch
// ---------------------------------------------------------------------------
extern "C" void kernel_launch(void* const* d_in, const int* in_sizes, int n_in,
                              void* d_out, int out_size) {
    const float* x      = (const float*)d_in[0];
    const int*   ei     = (const int*)d_in[1];
    const float* Zt     = (const float*)d_in[2];
    const int*   firstp = (const int*)d_in[3];
    const float* W_conv = (const float*)d_in[4];
    const float* b_conv = (const float*)d_in[5];
    const float* W_ir   = (const float*)d_in[6];
    const float* b_ir   = (const float*)d_in[7];
    const float* W_hr   = (const float*)d_in[8];
    const float* b_hr   = (const float*)d_in[9];
    const float* W_iz   = (const float*)d_in[10];
    const float* b_iz   = (const float*)d_in[11];
    const float* W_hz   = (const float*)d_in[12];
    const float* b_hz   = (const float*)d_in[13];
    const float* W_in   = (const float*)d_in[14];
    const float* b_in   = (const float*)d_in[15];
    const float* W_hn   = (const float*)d_in[16];
    const float* b_hn   = (const float*)d_in[17];
    const float* W_fc1  = (const float*)d_in[18];
    const float* b_fc1  = (const float*)d_in[19];
    const float* W_fc2  = (const float*)d_in[20];
    const float* b_fc2  = (const float*)d_in[21];

    const int n = in_sizes[0] / DIN;
    const int e = in_sizes[1] / 2;
    const int* rowp = ei;
    const int* colp = ei + e;

    float* out_final = (float*)d_out;
    float* out_zbar  = (float*)d_out + (size_t)n * OUTN;

    const int TPB = 256;
    const int B1 = (n + TPB - 1) / TPB;
    const int B2 = (e / 4 + TPB - 1) / TPB;
    const int nsb = (n + SCAN_BLK - 1) / SCAN_BLK;

    k12_xw_deg<<<B1 + B2, TPB>>>(x, W_conv, colp, n, e, B1);
    k3_dis<<<(n + TPB - 1) / TPB, TPB>>>(n);
    kscanA<<<nsb, 256>>>(n);
    kscanB<<<1, 1024>>>(nsb, n, e);
    kscanC<<<nsb, 256>>>(n);
    kreorder<<<(e / 4 + TPB - 1) / TPB, TPB>>>(rowp, colp, e);
    k4_gather<<<148 * 8, TPB>>>(2 * n);
    k5_gru<<<148 * 4, 128>>>(Zt, firstp, b_conv,
                             W_ir, b_ir, W_hr, b_hr,
                             W_iz, b_iz, W_hz, b_hz,
                             W_in, b_in, W_hn, b_hn,
                             W_fc1, b_fc1, W_fc2, b_fc2,
                             out_final, out_zbar, n);
}